// round 12
// baseline (speedup 1.0000x reference)
#include <cuda_runtime.h>
#include <cuda_bf16.h>
#include <cstdint>
#include <cstddef>

#define S_LEN  2048
#define DMODEL 1024
#define NHEAD  16
#define DK     64
#define NTOK   4096

// ===================== low-level helpers (base sm_103 target safe) =====================
__device__ __forceinline__ uint32_t smem_u32(const void* p) {
    uint32_t a;
    asm("{ .reg .u64 t; cvta.to.shared.u64 t, %1; cvt.u32.u64 %0, t; }" : "=r"(a) : "l"(p));
    return a;
}
#define LDSM4(d, addr) \
    asm volatile("ldmatrix.sync.aligned.m8n8.x4.shared.b16 {%0,%1,%2,%3}, [%4];" \
        : "=r"((d)[0]), "=r"((d)[1]), "=r"((d)[2]), "=r"((d)[3]) : "r"(addr))
#define MMA_BF16(c, a, b) \
    asm volatile("mma.sync.aligned.m16n8k16.row.col.f32.bf16.bf16.f32 " \
        "{%0,%1,%2,%3}, {%4,%5,%6,%7}, {%8,%9}, {%0,%1,%2,%3};" \
        : "+f"((c)[0]), "+f"((c)[1]), "+f"((c)[2]), "+f"((c)[3]) \
        : "r"((a)[0]), "r"((a)[1]), "r"((a)[2]), "r"((a)[3]), "r"((b)[0]), "r"((b)[1]))

#define BULK_CP(dst, src, size, mbar) \
    asm volatile("cp.async.bulk.shared::cluster.global.mbarrier::complete_tx::bytes " \
        "[%0], [%1], %2, [%3];" \
        :: "r"((uint32_t)(dst)), "l"(src), "r"((uint32_t)(size)), "r"((uint32_t)(mbar)) : "memory")
#define MBAR_INIT(addr, cnt) \
    asm volatile("mbarrier.init.shared.b64 [%0], %1;" :: "r"((uint32_t)(addr)), "r"((uint32_t)(cnt)) : "memory")
#define MBAR_EXPECT(addr, bytes) \
    asm volatile("mbarrier.arrive.expect_tx.shared.b64 _, [%0], %1;" \
        :: "r"((uint32_t)(addr)), "r"((uint32_t)(bytes)) : "memory")
#define FENCE_ASYNC_SHARED() asm volatile("fence.proxy.async.shared::cta;" ::: "memory")

__device__ __forceinline__ void mbar_wait(uint32_t mbar, int phase) {
    asm volatile(
        "{\n\t.reg .pred P1;\n\t"
        "WAIT_LOOP_%=:\n\t"
        "mbarrier.try_wait.parity.acquire.cta.shared::cta.b64 P1, [%0], %1, 0x989680;\n\t"
        "@P1 bra.uni WAIT_DONE_%=;\n\t"
        "bra.uni WAIT_LOOP_%=;\n\t"
        "WAIT_DONE_%=:\n\t}"
        :: "r"(mbar), "r"((uint32_t)phase) : "memory");
}

__device__ __forceinline__ void split2(float v, __nv_bfloat16& h, __nv_bfloat16& l) {
    h = __float2bfloat16(v);
    l = __float2bfloat16(v - __bfloat162float(h));
}
__device__ __forceinline__ void split_pack(float x, float y, uint32_t& hp, uint32_t& lp) {
    __nv_bfloat16 hx, lx, hy, ly;
    split2(x, hx, lx); split2(y, hy, ly);
    __nv_bfloat162 h2(hx, hy), l2(lx, ly);
    hp = *reinterpret_cast<uint32_t*>(&h2);
    lp = *reinterpret_cast<uint32_t*>(&l2);
}
__device__ __forceinline__ uint32_t swz(int r, int x) {
    return (uint32_t)(r * 128 + (x ^ ((r & 7) << 4)));
}

// ===================== scratch (all packed tile layouts) =====================
__device__ __nv_bfloat16 g_qh[NTOK*DMODEL], g_ql[NTOK*DMODEL];     // A-packed [32][16] tiles
__device__ __nv_bfloat16 g_kh[NTOK*DMODEL], g_kl[NTOK*DMODEL];
__device__ __nv_bfloat16 g_vh[NTOK*DMODEL], g_vl[NTOK*DMODEL];
__device__ __nv_bfloat16 g_Wqh[DMODEL*DMODEL], g_Wql[DMODEL*DMODEL]; // B-packed [8][16]
__device__ __nv_bfloat16 g_Wkh[DMODEL*DMODEL], g_Wkl[DMODEL*DMODEL];
__device__ __nv_bfloat16 g_Wvh[DMODEL*DMODEL], g_Wvl[DMODEL*DMODEL];
__device__ __nv_bfloat16 g_Woh[DMODEL*DMODEL], g_Wol[DMODEL*DMODEL];
__device__ __nv_bfloat16 g_qph[NTOK*DMODEL], g_qpl[NTOK*DMODEL];   // [b][qt16][h] 16KB tiles
__device__ __nv_bfloat16 g_kph[NTOK*DMODEL], g_kpl[NTOK*DMODEL];   // [b][kt32][h] 8KB tiles
__device__ __nv_bfloat16 g_vTh[NTOK*DMODEL], g_vTl[NTOK*DMODEL];   // [b][kt32][h] 8KB V^T tiles
__device__ __nv_bfloat16 g_ath[NTOK*DMODEL], g_atl[NTOK*DMODEL];   // A-packed [32][16]

// ===================== merged fp32 -> packed swizzled (bf16 hi, bf16 lo) =====================
__global__ __launch_bounds__(256) void cvt_all(
    const float* __restrict__ q, const float* __restrict__ k, const float* __restrict__ v,
    const float* __restrict__ Wq, const float* __restrict__ Wk,
    const float* __restrict__ Wv, const float* __restrict__ Wo,
    __nv_bfloat16* qh, __nv_bfloat16* ql, __nv_bfloat16* kh, __nv_bfloat16* kl,
    __nv_bfloat16* vh, __nv_bfloat16* vl,
    __nv_bfloat16* Wqh, __nv_bfloat16* Wql, __nv_bfloat16* Wkh, __nv_bfloat16* Wkl,
    __nv_bfloat16* Wvh, __nv_bfloat16* Wvl, __nv_bfloat16* Woh, __nv_bfloat16* Wol)
{
    int bid = blockIdx.x;
    const float* src; __nv_bfloat16 *hi, *lo; int lb;
    if      (bid < 4096)  { src = q;  hi = qh;  lo = ql;  lb = bid; }
    else if (bid < 8192)  { src = k;  hi = kh;  lo = kl;  lb = bid - 4096; }
    else if (bid < 12288) { src = v;  hi = vh;  lo = vl;  lb = bid - 8192; }
    else if (bid < 13312) { src = Wq; hi = Wqh; lo = Wql; lb = bid - 12288; }
    else if (bid < 14336) { src = Wk; hi = Wkh; lo = Wkl; lb = bid - 13312; }
    else if (bid < 15360) { src = Wv; hi = Wvh; lo = Wvl; lb = bid - 14336; }
    else                  { src = Wo; hi = Woh; lo = Wol; lb = bid - 15360; }
    int i = (lb * 256 + threadIdx.x) * 4;
    float4 val = *(const float4*)(src + i);
    uint32_t hp0, lp0, hp1, lp1;
    split_pack(val.x, val.y, hp0, lp0);
    split_pack(val.z, val.w, hp1, lp1);
    int row = i >> 10, kk = i & 1023;
    int mb = row >> 7, r = row & 127, kc = kk >> 6, c = kk & 63;
    size_t dst = (((size_t)mb * 16 + kc) << 14) + swz(r, c * 2);
    *(uint32_t*)((char*)hi + dst)     = hp0;
    *(uint32_t*)((char*)hi + dst + 4) = hp1;
    *(uint32_t*)((char*)lo + dst)     = lp0;
    *(uint32_t*)((char*)lo + dst + 4) = lp1;
}

// ===================== HMMA bf16x3 GEMM body (256x128 tile, BK=64, 16KB bulk copies) =====================
// 256 threads = 8 warps (64x64 warp tile). Stage = [Ahi0,Ahi1,Alo0,Alo1,Bhi,Blo] 6x16KB.
// ep: 0 fp32+bias | 1 Q-packed | 2 K-packed | 3 V^T-packed  (1-3: bf16 hi/lo (+bias)*scale)
#define G_TILE 16384
#define G_STAGE (6 * G_TILE)         // 98304
#define G_SMEM (1024 + 2 * G_STAGE)  // 197632

__device__ __forceinline__ void gemm_body(
    int ep,
    const char* Ah, const char* Al, const char* Bh, const char* Bl,
    float* C32, __nv_bfloat16* Chi, __nv_bfloat16* Clo,
    const float* bias, float scale, char* smem)
{
    const uint32_t sbase = smem_u32(smem);
    const uint32_t mb0 = sbase, mb1 = sbase + 16;
    const uint32_t dbase = sbase + 1024;

    const int tid = threadIdx.x;
    const int warp = tid >> 5, lane = tid & 31;
    const int wm0 = (warp >> 1) * 64, wn0 = (warp & 1) * 64;
    const int m0 = blockIdx.y * 256;
    const int n0 = blockIdx.x * 128;
    const uint32_t swx = (lane & 7) << 4;

    if (tid == 0) {
        MBAR_INIT(mb0, 1);
        MBAR_INIT(mb1, 1);
        FENCE_ASYNC_SHARED();
    }
    __syncthreads();

    auto load_chunk = [&](int c, int buf) {
        if (tid == 0) {
            const uint32_t s = dbase + buf * G_STAGE;
            const uint32_t mb = buf ? mb1 : mb0;
            MBAR_EXPECT(mb, G_STAGE);
            size_t at0 = ((size_t)((blockIdx.y * 2 + 0) * 16 + c)) << 14;
            size_t at1 = ((size_t)((blockIdx.y * 2 + 1) * 16 + c)) << 14;
            size_t bt  = ((size_t)(blockIdx.x * 16 + c)) << 14;
            BULK_CP(s,               Ah + at0, G_TILE, mb);
            BULK_CP(s + G_TILE,      Ah + at1, G_TILE, mb);
            BULK_CP(s + 2 * G_TILE,  Al + at0, G_TILE, mb);
            BULK_CP(s + 3 * G_TILE,  Al + at1, G_TILE, mb);
            BULK_CP(s + 4 * G_TILE,  Bh + bt,  G_TILE, mb);
            BULK_CP(s + 5 * G_TILE,  Bl + bt,  G_TILE, mb);
        }
    };

    float acc[4][8][4];
#pragma unroll
    for (int i = 0; i < 4; ++i)
#pragma unroll
        for (int j = 0; j < 8; ++j)
#pragma unroll
            for (int e = 0; e < 4; ++e) acc[i][j][e] = 0.f;

    const uint32_t aTile = (uint32_t)(wm0 >> 7) * G_TILE;       // 0 or 16KB
    const uint32_t aRow = ((wm0 & 127) + (lane & 15)) * 128;
    const int g = lane >> 3;
    const uint32_t bRow = (wn0 + (g >> 1) * 8 + (lane & 7)) * 128;
    const uint32_t xA = (lane >> 4) * 16;
    const uint32_t xB = (g & 1) * 16;

    load_chunk(0, 0);
    load_chunk(1, 1);

    int ph[2] = { 0, 0 };
    const int chunks = 16;
    for (int c = 0; c < chunks; ++c) {
        const int buf = c & 1;
        mbar_wait(buf ? mb1 : mb0, ph[buf]);
        ph[buf] ^= 1;

        const uint32_t s = dbase + buf * G_STAGE;
#pragma unroll
        for (int ks = 0; ks < 4; ++ks) {
            const uint32_t kb = ks * 32;
            uint32_t ah[4][4], al[4][4];
#pragma unroll
            for (int mt = 0; mt < 4; ++mt) {
                uint32_t off = aTile + aRow + mt * 2048 + ((xA + kb) ^ swx);
                LDSM4(ah[mt], s + off);
                LDSM4(al[mt], s + 2 * G_TILE + off);
            }
            uint32_t bh[8][2], bl[8][2];
#pragma unroll
            for (int ntp = 0; ntp < 4; ++ntp) {
                uint32_t off = bRow + ntp * 2048 + ((xB + kb) ^ swx);
                uint32_t t[4];
                LDSM4(t, s + 4 * G_TILE + off);
                bh[ntp*2][0] = t[0]; bh[ntp*2][1] = t[1];
                bh[ntp*2+1][0] = t[2]; bh[ntp*2+1][1] = t[3];
                LDSM4(t, s + 5 * G_TILE + off);
                bl[ntp*2][0] = t[0]; bl[ntp*2][1] = t[1];
                bl[ntp*2+1][0] = t[2]; bl[ntp*2+1][1] = t[3];
            }
#pragma unroll
            for (int mt = 0; mt < 4; ++mt)
#pragma unroll
                for (int nt = 0; nt < 8; ++nt) {
                    MMA_BF16(acc[mt][nt], ah[mt], bh[nt]);
                    MMA_BF16(acc[mt][nt], ah[mt], bl[nt]);
                    MMA_BF16(acc[mt][nt], al[mt], bh[nt]);
                }
        }
        __syncthreads();   // all reads of buf done before refill
        if (c + 2 < chunks) load_chunk(c + 2, buf);
    }

#pragma unroll
    for (int mt = 0; mt < 4; ++mt) {
#pragma unroll
        for (int nt = 0; nt < 8; ++nt) {
            int row0 = m0 + wm0 + mt * 16 + (lane >> 2);
            int row1 = row0 + 8;
            int col = n0 + wn0 + nt * 8 + (lane & 3) * 2;
            float p0 = acc[mt][nt][0], p1 = acc[mt][nt][1];
            float p2 = acc[mt][nt][2], p3 = acc[mt][nt][3];
            if (ep == 0) {
                float b0 = bias[col], b1 = bias[col + 1];
                *(float2*)&C32[(long long)row0 * DMODEL + col] = make_float2(p0 + b0, p1 + b1);
                *(float2*)&C32[(long long)row1 * DMODEL + col] = make_float2(p2 + b0, p3 + b1);
            } else if (ep == 1 || ep == 2) {
                float b0 = bias[col], b1 = bias[col + 1];
                float v0 = (p0 + b0) * scale, v1 = (p1 + b1) * scale;
                float v2 = (p2 + b0) * scale, v3 = (p3 + b1) * scale;
                int h = col >> 6, cc = col & 63;
                int rows[2] = { row0, row1 };
                uint32_t hps[2], lps[2];
                split_pack(v0, v1, hps[0], lps[0]);
                split_pack(v2, v3, hps[1], lps[1]);
#pragma unroll
                for (int e = 0; e < 2; ++e) {
                    int t = rows[e];
                    size_t dst;
                    if (ep == 1) {   // Q-packed: [b][qt128][h] 16KB
                        dst = ((((size_t)(t >> 11) * 16 + ((t & 2047) >> 7)) * 16 + h) << 14)
                            + swz(t & 127, cc * 2);
                    } else {         // K-packed: [b][kt64][h] 8KB
                        dst = ((((size_t)(t >> 11) * 32 + ((t & 2047) >> 6)) * 16 + h) << 13)
                            + swz(t & 63, cc * 2);
                    }
                    *(uint32_t*)((char*)Chi + dst) = hps[e];
                    *(uint32_t*)((char*)Clo + dst) = lps[e];
                }
            } else {  // ep == 3 : V^T-packed: [b][kt64][h] 8KB, rows=d cols=key
                float vals[4] = { p0, p1, p2, p3 };
                int rows[4] = { row0, row0, row1, row1 };
                int cols[4] = { col, col + 1, col, col + 1 };
#pragma unroll
                for (int e = 0; e < 4; ++e) {
                    float vv = vals[e] + bias[cols[e]];
                    __nv_bfloat16 h2, l2; split2(vv, h2, l2);
                    int t = rows[e];
                    int hh = cols[e] >> 6, d = cols[e] & 63;
                    size_t dst = ((((size_t)(t >> 11) * 32 + ((t & 2047) >> 6)) * 16 + hh) << 13)
                               + swz(d, (t & 63) * 2);
                    *(__nv_bfloat16*)((char*)Chi + dst) = h2;
                    *(__nv_bfloat16*)((char*)Clo + dst) = l2;
                }
            }
        }
    }
}

// merged Q/K/V projections: blockIdx.z selects operands
__global__ __launch_bounds__(256, 1) void proj_qkv(
    const __nv_bfloat16* qh, const __nv_bfloat16* ql,
    const __nv_bfloat16* kh, const __nv_bfloat16* kl,
    const __nv_bfloat16* vh, const __nv_bfloat16* vl,
    const __nv_bfloat16* Wqh, const __nv_bfloat16* Wql,
    const __nv_bfloat16* Wkh, const __nv_bfloat16* Wkl,
    const __nv_bfloat16* Wvh, const __nv_bfloat16* Wvl,
    const float* bq, const float* bk, const float* bv,
    __nv_bfloat16* qph, __nv_bfloat16* qpl,
    __nv_bfloat16* kph, __nv_bfloat16* kpl,
    __nv_bfloat16* vTh, __nv_bfloat16* vTl)
{
    extern __shared__ char smem[];
    int z = blockIdx.z;
    if (z == 0) {
        gemm_body(1, (const char*)qh, (const char*)ql, (const char*)Wqh, (const char*)Wql,
                  nullptr, qph, qpl, bq, 0.125f, smem);
    } else if (z == 1) {
        gemm_body(2, (const char*)kh, (const char*)kl, (const char*)Wkh, (const char*)Wkl,
                  nullptr, kph, kpl, bk, 1.0f, smem);
    } else {
        gemm_body(3, (const char*)vh, (const char*)vl, (const char*)Wvh, (const char*)Wvl,
                  nullptr, vTh, vTl, bv, 1.0f, smem);
    }
}

// final projection (fp32 out + bias)
__global__ __launch_bounds__(256, 1) void proj_out(
    const __nv_bfloat16* ath, const __nv_bfloat16* atl,
    const __nv_bfloat16* Woh, const __nv_bfloat16* Wol,
    const float* bo, float* out)
{
    extern __shared__ char smem[];
    gemm_body(0, (const char*)ath, (const char*)atl, (const char*)Woh, (const char*)Wol,
              out, nullptr, nullptr, bo, 1.0f, smem);
}

// ===================== fused flash attention (packed tiles, 8KB/16KB bulk copies) =====================
#define FQ_TILE 16384
#define FK_TILE 8192
#define FB_STAGE (4 * FK_TILE)                    // 32768
#define FB_SMEM (1024 + 2 * FQ_TILE + 2 * FB_STAGE)  // 99328

__global__ __launch_bounds__(128, 2) void flash_attn(
    const __nv_bfloat16* __restrict__ qh_, const __nv_bfloat16* __restrict__ ql_,
    const __nv_bfloat16* __restrict__ kh_, const __nv_bfloat16* __restrict__ kl_,
    const __nv_bfloat16* __restrict__ vth_, const __nv_bfloat16* __restrict__ vtl_,
    __nv_bfloat16* __restrict__ oh_, __nv_bfloat16* __restrict__ ol_)
{
    extern __shared__ char smem[];
    const uint32_t sb = smem_u32(smem);
    const uint32_t mbq = sb, mbk0 = sb + 16, mbk1 = sb + 32;
    const uint32_t db = sb + 1024;
    const int tid = threadIdx.x;
    const int warp = tid >> 5, lane = tid & 31;
    const int qt = blockIdx.x, h = blockIdx.y, b = blockIdx.z;
    const uint32_t swx = (lane & 7) << 4;

    const long long qrow0 = (long long)(b * S_LEN + qt * 128);
    const char* Qhg = (const char*)qh_ + ((((size_t)b * 16 + qt) * 16 + h) << 14);
    const char* Qlg = (const char*)ql_ + ((((size_t)b * 16 + qt) * 16 + h) << 14);
    const char* Khg = (const char*)kh_;
    const char* Klg = (const char*)kl_;
    const char* Vhg = (const char*)vth_;
    const char* Vlg = (const char*)vtl_;

    if (tid == 0) {
        MBAR_INIT(mbq, 1);
        MBAR_INIT(mbk0, 1);
        MBAR_INIT(mbk1, 1);
        FENCE_ASYNC_SHARED();
    }
    __syncthreads();

    auto loadQ = [&]() {
        if (tid == 0) {
            MBAR_EXPECT(mbq, 2 * FQ_TILE);
            BULK_CP(db,           Qhg, FQ_TILE, mbq);
            BULK_CP(db + FQ_TILE, Qlg, FQ_TILE, mbq);
        }
    };
    auto loadKV = [&](int kt, int buf) {
        if (tid == 0) {
            const uint32_t s = db + 2 * FQ_TILE + buf * FB_STAGE;
            const uint32_t mb = buf ? mbk1 : mbk0;
            MBAR_EXPECT(mb, FB_STAGE);
            size_t toff = (((size_t)b * 32 + kt) * 16 + h) << 13;
            BULK_CP(s,               Khg + toff, FK_TILE, mb);
            BULK_CP(s + FK_TILE,     Klg + toff, FK_TILE, mb);
            BULK_CP(s + 2 * FK_TILE, Vhg + toff, FK_TILE, mb);
            BULK_CP(s + 3 * FK_TILE, Vlg + toff, FK_TILE, mb);
        }
    };

    float accO[2][8][4];
#pragma unroll
    for (int mt = 0; mt < 2; ++mt)
#pragma unroll
        for (int i = 0; i < 8; ++i)
#pragma unroll
            for (int e = 0; e < 4; ++e) accO[mt][i][e] = 0.f;
    float fm[2][2] = {{-1e30f, -1e30f}, {-1e30f, -1e30f}};
    float fl[2][2] = {{0.f, 0.f}, {0.f, 0.f}};
    uint32_t qfh[2][4][4];

    loadQ();
    loadKV(0, 0);
    loadKV(1, 1);

    const uint32_t qRow = (warp * 32 + (lane & 15)) * 128;
    const uint32_t xQ = (lane >> 4) * 16;
    const int g = lane >> 3;
    const uint32_t kRow = ((g >> 1) * 8 + (lane & 7)) * 128;
    const uint32_t xKV = (g & 1) * 16;

    int ph[2] = { 0, 0 };
    const int NT64 = S_LEN / 64;   // 32
    for (int kt = 0; kt < NT64; ++kt) {
        const int buf = kt & 1;
        mbar_wait(buf ? mbk1 : mbk0, ph[buf]);
        ph[buf] ^= 1;
        if (kt == 0) {
            mbar_wait(mbq, 0);
#pragma unroll
            for (int mt = 0; mt < 2; ++mt)
#pragma unroll
                for (int ks = 0; ks < 4; ++ks)
                    LDSM4(qfh[mt][ks], db + qRow + mt * 2048 + ((xQ + ks * 32) ^ swx));
        }
        const uint32_t s = db + 2 * FQ_TILE + buf * FB_STAGE;

        // ---- S = Q @ K^T over 64 keys (3 products) ----
        float accS[2][8][4];
#pragma unroll
        for (int mt = 0; mt < 2; ++mt)
#pragma unroll
            for (int i = 0; i < 8; ++i)
#pragma unroll
                for (int e = 0; e < 4; ++e) accS[mt][i][e] = 0.f;
#pragma unroll
        for (int ks = 0; ks < 4; ++ks) {
            uint32_t qfl0[4], qfl1[4];
            LDSM4(qfl0, db + FQ_TILE + qRow + 0 * 2048 + ((xQ + ks * 32) ^ swx));
            LDSM4(qfl1, db + FQ_TILE + qRow + 1 * 2048 + ((xQ + ks * 32) ^ swx));
#pragma unroll
            for (int ntp = 0; ntp < 4; ++ntp) {
                const uint32_t kA = s + kRow + ntp * 2048 + ((xKV + ks * 32) ^ swx);
                uint32_t th[4], tl[4];
                LDSM4(th, kA);
                LDSM4(tl, kA + FK_TILE);
                uint32_t bh0[2] = { th[0], th[1] }, bh1[2] = { th[2], th[3] };
                uint32_t bl0[2] = { tl[0], tl[1] }, bl1[2] = { tl[2], tl[3] };
                MMA_BF16(accS[0][2*ntp],   qfh[0][ks], bh0);
                MMA_BF16(accS[0][2*ntp],   qfh[0][ks], bl0);
                MMA_BF16(accS[0][2*ntp],   qfl0,       bh0);
                MMA_BF16(accS[0][2*ntp+1], qfh[0][ks], bh1);
                MMA_BF16(accS[0][2*ntp+1], qfh[0][ks], bl1);
                MMA_BF16(accS[0][2*ntp+1], qfl0,       bh1);
                MMA_BF16(accS[1][2*ntp],   qfh[1][ks], bh0);
                MMA_BF16(accS[1][2*ntp],   qfh[1][ks], bl0);
                MMA_BF16(accS[1][2*ntp],   qfl1,       bh0);
                MMA_BF16(accS[1][2*ntp+1], qfh[1][ks], bh1);
                MMA_BF16(accS[1][2*ntp+1], qfh[1][ks], bl1);
                MMA_BF16(accS[1][2*ntp+1], qfl1,       bh1);
            }
        }

        // ---- online softmax ----
#pragma unroll
        for (int mt = 0; mt < 2; ++mt) {
            float mx0 = -1e30f, mx1 = -1e30f;
#pragma unroll
            for (int nt = 0; nt < 8; ++nt) {
                mx0 = fmaxf(mx0, fmaxf(accS[mt][nt][0], accS[mt][nt][1]));
                mx1 = fmaxf(mx1, fmaxf(accS[mt][nt][2], accS[mt][nt][3]));
            }
            mx0 = fmaxf(mx0, __shfl_xor_sync(0xffffffffu, mx0, 1));
            mx0 = fmaxf(mx0, __shfl_xor_sync(0xffffffffu, mx0, 2));
            mx1 = fmaxf(mx1, __shfl_xor_sync(0xffffffffu, mx1, 1));
            mx1 = fmaxf(mx1, __shfl_xor_sync(0xffffffffu, mx1, 2));
            float mn0 = fmaxf(fm[mt][0], mx0), mn1 = fmaxf(fm[mt][1], mx1);
            float c0 = __expf(fm[mt][0] - mn0), c1 = __expf(fm[mt][1] - mn1);
            fm[mt][0] = mn0; fm[mt][1] = mn1;
            float s0 = 0.f, s1 = 0.f;
#pragma unroll
            for (int nt = 0; nt < 8; ++nt) {
                accS[mt][nt][0] = __expf(accS[mt][nt][0] - mn0);
                accS[mt][nt][1] = __expf(accS[mt][nt][1] - mn0);
                accS[mt][nt][2] = __expf(accS[mt][nt][2] - mn1);
                accS[mt][nt][3] = __expf(accS[mt][nt][3] - mn1);
                s0 += accS[mt][nt][0] + accS[mt][nt][1];
                s1 += accS[mt][nt][2] + accS[mt][nt][3];
            }
            s0 += __shfl_xor_sync(0xffffffffu, s0, 1);
            s0 += __shfl_xor_sync(0xffffffffu, s0, 2);
            s1 += __shfl_xor_sync(0xffffffffu, s1, 1);
            s1 += __shfl_xor_sync(0xffffffffu, s1, 2);
            fl[mt][0] = fl[mt][0] * c0 + s0;
            fl[mt][1] = fl[mt][1] * c1 + s1;
#pragma unroll
            for (int nt = 0; nt < 8; ++nt) {
                accO[mt][nt][0] *= c0; accO[mt][nt][1] *= c0;
                accO[mt][nt][2] *= c1; accO[mt][nt][3] *= c1;
            }
        }

        // ---- O += P @ V ----
#pragma unroll
        for (int kg = 0; kg < 4; ++kg) {
            uint32_t pah[2][4], pal[2][4];
#pragma unroll
            for (int mt = 0; mt < 2; ++mt) {
                split_pack(accS[mt][2*kg][0],   accS[mt][2*kg][1],   pah[mt][0], pal[mt][0]);
                split_pack(accS[mt][2*kg][2],   accS[mt][2*kg][3],   pah[mt][1], pal[mt][1]);
                split_pack(accS[mt][2*kg+1][0], accS[mt][2*kg+1][1], pah[mt][2], pal[mt][2]);
                split_pack(accS[mt][2*kg+1][2], accS[mt][2*kg+1][3], pah[mt][3], pal[mt][3]);
            }
#pragma unroll
            for (int ntp = 0; ntp < 4; ++ntp) {
                const uint32_t vA = s + 2 * FK_TILE + kRow + ntp * 2048 + ((xKV + kg * 32) ^ swx);
                uint32_t th[4], tl[4];
                LDSM4(th, vA);
                LDSM4(tl, vA + FK_TILE);
                uint32_t bh0[2] = { th[0], th[1] }, bh1[2] = { th[2], th[3] };
                uint32_t bl0[2] = { tl[0], tl[1] }, bl1[2] = { tl[2], tl[3] };
#pragma unroll
                for (int mt = 0; mt < 2; ++mt) {
                    MMA_BF16(accO[mt][2*ntp],   pah[mt], bh0);
                    MMA_BF16(accO[mt][2*ntp],   pah[mt], bl0);
                    MMA_BF16(accO[mt][2*ntp],   pal[mt], bh0);
                    MMA_BF16(accO[mt][2*ntp+1], pah[mt], bh1);
                    MMA_BF16(accO[mt][2*ntp+1], pah[mt], bl1);
                    MMA_BF16(accO[mt][2*ntp+1], pal[mt], bh1);
                }
            }
        }
        __syncthreads();
        if (kt + 2 < NT64) loadKV(kt + 2, buf);
    }

    // ---- epilogue: write into A-packed layout for proj_out (k_chunk = h) ----
#pragma unroll
    for (int mt = 0; mt < 2; ++mt) {
        const float inv0 = 1.0f / fl[mt][0], inv1 = 1.0f / fl[mt][1];
        const long long tok0 = qrow0 + warp * 32 + mt * 16 + (lane >> 2);
        const int cb = (lane & 3) * 2;
#pragma unroll
        for (int nt = 0; nt < 8; ++nt) {
            int d = cb + nt * 8;
            uint32_t hp, lp;
            long long t0 = tok0, t1 = tok0 + 8;
            size_t dst0 = ((((size_t)(t0 >> 7)) * 16 + h) << 14) + swz((int)(t0 & 127), d * 2);
            size_t dst1 = ((((size_t)(t1 >> 7)) * 16 + h) << 14) + swz((int)(t1 & 127), d * 2);
            split_pack(accO[mt][nt][0] * inv0, accO[mt][nt][1] * inv0, hp, lp);
            *(uint32_t*)((char*)oh_ + dst0) = hp;
            *(uint32_t*)((char*)ol_ + dst0) = lp;
            split_pack(accO[mt][nt][2] * inv1, accO[mt][nt][3] * inv1, hp, lp);
            *(uint32_t*)((char*)oh_ + dst1) = hp;
            *(uint32_t*)((char*)ol_ + dst1) = lp;
        }
    }
}

// ===================== host =====================
static inline void* sym(const void* s) { void* p; cudaGetSymbolAddress(&p, s); return p; }

extern "C" void kernel_launch(void* const* d_in, const int* in_sizes, int n_in,
                              void* d_out, int out_size) {
    const float* v  = (const float*)d_in[0];
    const float* k  = (const float*)d_in[1];
    const float* q  = (const float*)d_in[2];
    const float* Wv = (const float*)d_in[3];
    const float* bv = (const float*)d_in[4];
    const float* Wk = (const float*)d_in[5];
    const float* bk = (const float*)d_in[6];
    const float* Wq = (const float*)d_in[7];
    const float* bq = (const float*)d_in[8];
    const float* Wo = (const float*)d_in[9];
    const float* bo = (const float*)d_in[10];

    __nv_bfloat16 *qh=(__nv_bfloat16*)sym(g_qh), *ql=(__nv_bfloat16*)sym(g_ql);
    __nv_bfloat16 *kh=(__nv_bfloat16*)sym(g_kh), *kl=(__nv_bfloat16*)sym(g_kl);
    __nv_bfloat16 *vh=(__nv_bfloat16*)sym(g_vh), *vl=(__nv_bfloat16*)sym(g_vl);
    __nv_bfloat16 *Wqh=(__nv_bfloat16*)sym(g_Wqh), *Wql=(__nv_bfloat16*)sym(g_Wql);
    __nv_bfloat16 *Wkh=(__nv_bfloat16*)sym(g_Wkh), *Wkl=(__nv_bfloat16*)sym(g_Wkl);
    __nv_bfloat16 *Wvh=(__nv_bfloat16*)sym(g_Wvh), *Wvl=(__nv_bfloat16*)sym(g_Wvl);
    __nv_bfloat16 *Woh=(__nv_bfloat16*)sym(g_Woh), *Wol=(__nv_bfloat16*)sym(g_Wol);
    __nv_bfloat16 *qph=(__nv_bfloat16*)sym(g_qph), *qpl=(__nv_bfloat16*)sym(g_qpl);
    __nv_bfloat16 *kph=(__nv_bfloat16*)sym(g_kph), *kpl=(__nv_bfloat16*)sym(g_kpl);
    __nv_bfloat16 *vTh=(__nv_bfloat16*)sym(g_vTh), *vTl=(__nv_bfloat16*)sym(g_vTl);
    __nv_bfloat16 *ath=(__nv_bfloat16*)sym(g_ath), *atl=(__nv_bfloat16*)sym(g_atl);

    cudaFuncSetAttribute(proj_qkv, cudaFuncAttributeMaxDynamicSharedMemorySize, G_SMEM);
    cudaFuncSetAttribute(proj_out, cudaFuncAttributeMaxDynamicSharedMemorySize, G_SMEM);
    cudaFuncSetAttribute(flash_attn, cudaFuncAttributeMaxDynamicSharedMemorySize, FB_SMEM);

    // launch 0: merged hi/lo splits into packed+swizzled layouts
    cvt_all<<<16384, 256>>>(q, k, v, Wq, Wk, Wv, Wo,
                            qh, ql, kh, kl, vh, vl,
                            Wqh, Wql, Wkh, Wkl, Wvh, Wvl, Woh, Wol);

    // launch 1: merged Q/K/V projections (256x128 tiles)
    proj_qkv<<<dim3(8, 16, 3), 256, G_SMEM>>>(
        qh, ql, kh, kl, vh, vl,
        Wqh, Wql, Wkh, Wkl, Wvh, Wvl,
        bq, bk, bv, qph, qpl, kph, kpl, vTh, vTl);

    // launch 2: fused flash attention (2 CTA/SM)
    flash_attn<<<dim3(S_LEN / 128, NHEAD, 2), 128, FB_SMEM>>>(
        qph, qpl, kph, kpl, vTh, vTl, ath, atl);

    // launch 3: final projection (256x128 tiles, 128 CTAs = 1 wave)
    proj_out<<<dim3(8, 16), 256, G_SMEM>>>(ath, atl, Woh, Wol, bo, (float*)d_out);
}

// round 14
// speedup vs baseline: 1.5005x; 1.5005x over previous
#include <cuda_runtime.h>
#include <cuda_bf16.h>
#include <cstdint>
#include <cstddef>

#define S_LEN  2048
#define DMODEL 1024
#define NHEAD  16
#define DK     64
#define NTOK   4096

// ===================== low-level helpers (base sm_103 target safe) =====================
__device__ __forceinline__ uint32_t smem_u32(const void* p) {
    uint32_t a;
    asm("{ .reg .u64 t; cvta.to.shared.u64 t, %1; cvt.u32.u64 %0, t; }" : "=r"(a) : "l"(p));
    return a;
}
#define LDSM4(d, addr) \
    asm volatile("ldmatrix.sync.aligned.m8n8.x4.shared.b16 {%0,%1,%2,%3}, [%4];" \
        : "=r"((d)[0]), "=r"((d)[1]), "=r"((d)[2]), "=r"((d)[3]) : "r"(addr))
#define MMA_BF16(c, a, b) \
    asm volatile("mma.sync.aligned.m16n8k16.row.col.f32.bf16.bf16.f32 " \
        "{%0,%1,%2,%3}, {%4,%5,%6,%7}, {%8,%9}, {%0,%1,%2,%3};" \
        : "+f"((c)[0]), "+f"((c)[1]), "+f"((c)[2]), "+f"((c)[3]) \
        : "r"((a)[0]), "r"((a)[1]), "r"((a)[2]), "r"((a)[3]), "r"((b)[0]), "r"((b)[1]))

#define BULK_CP(dst, src, size, mbar) \
    asm volatile("cp.async.bulk.shared::cluster.global.mbarrier::complete_tx::bytes " \
        "[%0], [%1], %2, [%3];" \
        :: "r"((uint32_t)(dst)), "l"(src), "r"((uint32_t)(size)), "r"((uint32_t)(mbar)) : "memory")
#define MBAR_INIT(addr, cnt) \
    asm volatile("mbarrier.init.shared.b64 [%0], %1;" :: "r"((uint32_t)(addr)), "r"((uint32_t)(cnt)) : "memory")
#define MBAR_EXPECT(addr, bytes) \
    asm volatile("mbarrier.arrive.expect_tx.shared.b64 _, [%0], %1;" \
        :: "r"((uint32_t)(addr)), "r"((uint32_t)(bytes)) : "memory")
#define FENCE_ASYNC_SHARED() asm volatile("fence.proxy.async.shared::cta;" ::: "memory")

__device__ __forceinline__ void mbar_wait(uint32_t mbar, int phase) {
    asm volatile(
        "{\n\t.reg .pred P1;\n\t"
        "WAIT_LOOP_%=:\n\t"
        "mbarrier.try_wait.parity.acquire.cta.shared::cta.b64 P1, [%0], %1, 0x989680;\n\t"
        "@P1 bra.uni WAIT_DONE_%=;\n\t"
        "bra.uni WAIT_LOOP_%=;\n\t"
        "WAIT_DONE_%=:\n\t}"
        :: "r"(mbar), "r"((uint32_t)phase) : "memory");
}

__device__ __forceinline__ void split2(float v, __nv_bfloat16& h, __nv_bfloat16& l) {
    h = __float2bfloat16(v);
    l = __float2bfloat16(v - __bfloat162float(h));
}
__device__ __forceinline__ void split_pack(float x, float y, uint32_t& hp, uint32_t& lp) {
    __nv_bfloat16 hx, lx, hy, ly;
    split2(x, hx, lx); split2(y, hy, ly);
    __nv_bfloat162 h2(hx, hy), l2(lx, ly);
    hp = *reinterpret_cast<uint32_t*>(&h2);
    lp = *reinterpret_cast<uint32_t*>(&l2);
}
__device__ __forceinline__ uint32_t swz(int r, int x) {
    return (uint32_t)(r * 128 + (x ^ ((r & 7) << 4)));
}

// ===================== scratch (all packed tile layouts) =====================
__device__ __nv_bfloat16 g_qh[NTOK*DMODEL], g_ql[NTOK*DMODEL];     // A-packed [32][16] tiles
__device__ __nv_bfloat16 g_kh[NTOK*DMODEL], g_kl[NTOK*DMODEL];
__device__ __nv_bfloat16 g_vh[NTOK*DMODEL], g_vl[NTOK*DMODEL];
__device__ __nv_bfloat16 g_Wqh[DMODEL*DMODEL], g_Wql[DMODEL*DMODEL]; // B-packed [8][16]
__device__ __nv_bfloat16 g_Wkh[DMODEL*DMODEL], g_Wkl[DMODEL*DMODEL];
__device__ __nv_bfloat16 g_Wvh[DMODEL*DMODEL], g_Wvl[DMODEL*DMODEL];
__device__ __nv_bfloat16 g_Woh[DMODEL*DMODEL], g_Wol[DMODEL*DMODEL];
__device__ __nv_bfloat16 g_qph[NTOK*DMODEL], g_qpl[NTOK*DMODEL];   // [b][qt16][h] 16KB tiles
__device__ __nv_bfloat16 g_kph[NTOK*DMODEL], g_kpl[NTOK*DMODEL];   // [b][kt32][h] 8KB tiles
__device__ __nv_bfloat16 g_vTh[NTOK*DMODEL], g_vTl[NTOK*DMODEL];   // [b][kt32][h] 8KB V^T tiles
__device__ __nv_bfloat16 g_ath[NTOK*DMODEL], g_atl[NTOK*DMODEL];   // A-packed [32][16]

// ===================== merged fp32 -> packed swizzled (bf16 hi, bf16 lo) =====================
__global__ __launch_bounds__(256) void cvt_all(
    const float* __restrict__ q, const float* __restrict__ k, const float* __restrict__ v,
    const float* __restrict__ Wq, const float* __restrict__ Wk,
    const float* __restrict__ Wv, const float* __restrict__ Wo,
    __nv_bfloat16* qh, __nv_bfloat16* ql, __nv_bfloat16* kh, __nv_bfloat16* kl,
    __nv_bfloat16* vh, __nv_bfloat16* vl,
    __nv_bfloat16* Wqh, __nv_bfloat16* Wql, __nv_bfloat16* Wkh, __nv_bfloat16* Wkl,
    __nv_bfloat16* Wvh, __nv_bfloat16* Wvl, __nv_bfloat16* Woh, __nv_bfloat16* Wol)
{
    int bid = blockIdx.x;
    const float* src; __nv_bfloat16 *hi, *lo; int lb;
    if      (bid < 4096)  { src = q;  hi = qh;  lo = ql;  lb = bid; }
    else if (bid < 8192)  { src = k;  hi = kh;  lo = kl;  lb = bid - 4096; }
    else if (bid < 12288) { src = v;  hi = vh;  lo = vl;  lb = bid - 8192; }
    else if (bid < 13312) { src = Wq; hi = Wqh; lo = Wql; lb = bid - 12288; }
    else if (bid < 14336) { src = Wk; hi = Wkh; lo = Wkl; lb = bid - 13312; }
    else if (bid < 15360) { src = Wv; hi = Wvh; lo = Wvl; lb = bid - 14336; }
    else                  { src = Wo; hi = Woh; lo = Wol; lb = bid - 15360; }
    int i = (lb * 256 + threadIdx.x) * 4;
    float4 val = *(const float4*)(src + i);
    uint32_t hp0, lp0, hp1, lp1;
    split_pack(val.x, val.y, hp0, lp0);
    split_pack(val.z, val.w, hp1, lp1);
    int row = i >> 10, kk = i & 1023;
    int mb = row >> 7, r = row & 127, kc = kk >> 6, c = kk & 63;
    size_t dst = (((size_t)mb * 16 + kc) << 14) + swz(r, c * 2);
    *(uint32_t*)((char*)hi + dst)     = hp0;
    *(uint32_t*)((char*)hi + dst + 4) = hp1;
    *(uint32_t*)((char*)lo + dst)     = lp0;
    *(uint32_t*)((char*)lo + dst + 4) = lp1;
}

// ===================== HMMA bf16x3 GEMM body (128x128 tile, BK=64, 3-stage bulk pipeline) =====================
// 256 threads = 8 warps (64x32 warp tile). Stage = [Ahi, Alo, Bhi, Blo] 4x16KB.
// ep: 0 fp32+bias | 1 Q-packed | 2 K-packed | 3 V^T-packed  (1-3: bf16 hi/lo (+bias)*scale)
#define G_TILE 16384
#define G_STAGE (4 * G_TILE)         // 65536
#define G_NSTG 3
#define G_SMEM (1024 + G_NSTG * G_STAGE)  // 197632

__device__ __forceinline__ void gemm_body(
    int ep,
    const char* Ah, const char* Al, const char* Bh, const char* Bl,
    float* C32, __nv_bfloat16* Chi, __nv_bfloat16* Clo,
    const float* bias, float scale, char* smem)
{
    const uint32_t sbase = smem_u32(smem);
    const uint32_t dbase = sbase + 1024;

    const int tid = threadIdx.x;
    const int warp = tid >> 5, lane = tid & 31;
    const int wm0 = (warp >> 2) * 64, wn0 = (warp & 3) * 32;
    const int m0 = blockIdx.y * 128;
    const int n0 = blockIdx.x * 128;
    const uint32_t swx = (lane & 7) << 4;

    if (tid == 0) {
        MBAR_INIT(sbase, 1);
        MBAR_INIT(sbase + 16, 1);
        MBAR_INIT(sbase + 32, 1);
        FENCE_ASYNC_SHARED();
    }
    __syncthreads();

    auto load_chunk = [&](int c, int stg) {
        if (tid == 0) {
            const uint32_t s = dbase + stg * G_STAGE;
            const uint32_t mb = sbase + stg * 16;
            MBAR_EXPECT(mb, G_STAGE);
            size_t at = ((size_t)(blockIdx.y * 16 + c)) << 14;
            size_t bt = ((size_t)(blockIdx.x * 16 + c)) << 14;
            BULK_CP(s,               Ah + at, G_TILE, mb);
            BULK_CP(s + G_TILE,      Al + at, G_TILE, mb);
            BULK_CP(s + 2 * G_TILE,  Bh + bt, G_TILE, mb);
            BULK_CP(s + 3 * G_TILE,  Bl + bt, G_TILE, mb);
        }
    };

    float acc[4][4][4];
#pragma unroll
    for (int i = 0; i < 4; ++i)
#pragma unroll
        for (int j = 0; j < 4; ++j)
#pragma unroll
            for (int e = 0; e < 4; ++e) acc[i][j][e] = 0.f;

    const uint32_t aRow = (wm0 + (lane & 15)) * 128;
    const int g = lane >> 3;
    const uint32_t bRow = (wn0 + (g >> 1) * 8 + (lane & 7)) * 128;
    const uint32_t xA = (lane >> 4) * 16;
    const uint32_t xB = (g & 1) * 16;

    load_chunk(0, 0);
    load_chunk(1, 1);
    load_chunk(2, 2);

    int ph[G_NSTG] = { 0, 0, 0 };
    int stg = 0;
    const int chunks = 16;
    for (int c = 0; c < chunks; ++c) {
        mbar_wait(sbase + stg * 16, ph[stg]);
        ph[stg] ^= 1;

        const uint32_t s = dbase + stg * G_STAGE;
#pragma unroll
        for (int ks = 0; ks < 4; ++ks) {
            const uint32_t kb = ks * 32;
            uint32_t ah[4][4], al[4][4];
#pragma unroll
            for (int mt = 0; mt < 4; ++mt) {
                uint32_t off = aRow + mt * 2048 + ((xA + kb) ^ swx);
                LDSM4(ah[mt], s + off);
                LDSM4(al[mt], s + G_TILE + off);
            }
            uint32_t bh[4][2], bl[4][2];
#pragma unroll
            for (int ntp = 0; ntp < 2; ++ntp) {
                uint32_t off = bRow + ntp * 2048 + ((xB + kb) ^ swx);
                uint32_t t[4];
                LDSM4(t, s + 2 * G_TILE + off);
                bh[ntp*2][0] = t[0]; bh[ntp*2][1] = t[1];
                bh[ntp*2+1][0] = t[2]; bh[ntp*2+1][1] = t[3];
                LDSM4(t, s + 3 * G_TILE + off);
                bl[ntp*2][0] = t[0]; bl[ntp*2][1] = t[1];
                bl[ntp*2+1][0] = t[2]; bl[ntp*2+1][1] = t[3];
            }
#pragma unroll
            for (int mt = 0; mt < 4; ++mt)
#pragma unroll
                for (int nt = 0; nt < 4; ++nt) {
                    MMA_BF16(acc[mt][nt], ah[mt], bh[nt]);
                    MMA_BF16(acc[mt][nt], ah[mt], bl[nt]);
                    MMA_BF16(acc[mt][nt], al[mt], bh[nt]);
                }
        }
        __syncthreads();   // all reads of stg done before refill
        if (c + G_NSTG < chunks) load_chunk(c + G_NSTG, stg);
        stg = (stg + 1 == G_NSTG) ? 0 : stg + 1;
    }

#pragma unroll
    for (int mt = 0; mt < 4; ++mt) {
#pragma unroll
        for (int nt = 0; nt < 4; ++nt) {
            int row0 = m0 + wm0 + mt * 16 + (lane >> 2);
            int row1 = row0 + 8;
            int col = n0 + wn0 + nt * 8 + (lane & 3) * 2;
            float p0 = acc[mt][nt][0], p1 = acc[mt][nt][1];
            float p2 = acc[mt][nt][2], p3 = acc[mt][nt][3];
            if (ep == 0) {
                float b0 = bias[col], b1 = bias[col + 1];
                *(float2*)&C32[(long long)row0 * DMODEL + col] = make_float2(p0 + b0, p1 + b1);
                *(float2*)&C32[(long long)row1 * DMODEL + col] = make_float2(p2 + b0, p3 + b1);
            } else if (ep == 1 || ep == 2) {
                float b0 = bias[col], b1 = bias[col + 1];
                float v0 = (p0 + b0) * scale, v1 = (p1 + b1) * scale;
                float v2 = (p2 + b0) * scale, v3 = (p3 + b1) * scale;
                int h = col >> 6, cc = col & 63;
                int rows[2] = { row0, row1 };
                uint32_t hps[2], lps[2];
                split_pack(v0, v1, hps[0], lps[0]);
                split_pack(v2, v3, hps[1], lps[1]);
#pragma unroll
                for (int e = 0; e < 2; ++e) {
                    int t = rows[e];
                    size_t dst;
                    if (ep == 1) {   // Q-packed: [b][qt128][h] 16KB
                        dst = ((((size_t)(t >> 11) * 16 + ((t & 2047) >> 7)) * 16 + h) << 14)
                            + swz(t & 127, cc * 2);
                    } else {         // K-packed: [b][kt64][h] 8KB
                        dst = ((((size_t)(t >> 11) * 32 + ((t & 2047) >> 6)) * 16 + h) << 13)
                            + swz(t & 63, cc * 2);
                    }
                    *(uint32_t*)((char*)Chi + dst) = hps[e];
                    *(uint32_t*)((char*)Clo + dst) = lps[e];
                }
            } else {  // ep == 3 : V^T-packed: [b][kt64][h] 8KB, rows=d cols=key
                float vals[4] = { p0, p1, p2, p3 };
                int rows[4] = { row0, row0, row1, row1 };
                int cols[4] = { col, col + 1, col, col + 1 };
#pragma unroll
                for (int e = 0; e < 4; ++e) {
                    float vv = vals[e] + bias[cols[e]];
                    __nv_bfloat16 h2, l2; split2(vv, h2, l2);
                    int t = rows[e];
                    int hh = cols[e] >> 6, d = cols[e] & 63;
                    size_t dst = ((((size_t)(t >> 11) * 32 + ((t & 2047) >> 6)) * 16 + hh) << 13)
                               + swz(d, (t & 63) * 2);
                    *(__nv_bfloat16*)((char*)Chi + dst) = h2;
                    *(__nv_bfloat16*)((char*)Clo + dst) = l2;
                }
            }
        }
    }
}

// merged Q/K/V projections: blockIdx.z selects operands
__global__ __launch_bounds__(256, 1) void proj_qkv(
    const __nv_bfloat16* qh, const __nv_bfloat16* ql,
    const __nv_bfloat16* kh, const __nv_bfloat16* kl,
    const __nv_bfloat16* vh, const __nv_bfloat16* vl,
    const __nv_bfloat16* Wqh, const __nv_bfloat16* Wql,
    const __nv_bfloat16* Wkh, const __nv_bfloat16* Wkl,
    const __nv_bfloat16* Wvh, const __nv_bfloat16* Wvl,
    const float* bq, const float* bk, const float* bv,
    __nv_bfloat16* qph, __nv_bfloat16* qpl,
    __nv_bfloat16* kph, __nv_bfloat16* kpl,
    __nv_bfloat16* vTh, __nv_bfloat16* vTl)
{
    extern __shared__ char smem[];
    int z = blockIdx.z;
    if (z == 0) {
        gemm_body(1, (const char*)qh, (const char*)ql, (const char*)Wqh, (const char*)Wql,
                  nullptr, qph, qpl, bq, 0.125f, smem);
    } else if (z == 1) {
        gemm_body(2, (const char*)kh, (const char*)kl, (const char*)Wkh, (const char*)Wkl,
                  nullptr, kph, kpl, bk, 1.0f, smem);
    } else {
        gemm_body(3, (const char*)vh, (const char*)vl, (const char*)Wvh, (const char*)Wvl,
                  nullptr, vTh, vTl, bv, 1.0f, smem);
    }
}

// final projection (fp32 out + bias)
__global__ __launch_bounds__(256, 1) void proj_out(
    const __nv_bfloat16* ath, const __nv_bfloat16* atl,
    const __nv_bfloat16* Woh, const __nv_bfloat16* Wol,
    const float* bo, float* out)
{
    extern __shared__ char smem[];
    gemm_body(0, (const char*)ath, (const char*)atl, (const char*)Woh, (const char*)Wol,
              out, nullptr, nullptr, bo, 1.0f, smem);
}

// ===================== fused flash attention (packed tiles, 8KB/16KB bulk copies) =====================
#define FQ_TILE 16384
#define FK_TILE 8192
#define FB_STAGE (4 * FK_TILE)                    // 32768
#define FB_SMEM (1024 + 2 * FQ_TILE + 2 * FB_STAGE)  // 99328

__global__ __launch_bounds__(128, 2) void flash_attn(
    const __nv_bfloat16* __restrict__ qh_, const __nv_bfloat16* __restrict__ ql_,
    const __nv_bfloat16* __restrict__ kh_, const __nv_bfloat16* __restrict__ kl_,
    const __nv_bfloat16* __restrict__ vth_, const __nv_bfloat16* __restrict__ vtl_,
    __nv_bfloat16* __restrict__ oh_, __nv_bfloat16* __restrict__ ol_)
{
    extern __shared__ char smem[];
    const uint32_t sb = smem_u32(smem);
    const uint32_t mbq = sb, mbk0 = sb + 16, mbk1 = sb + 32;
    const uint32_t db = sb + 1024;
    const int tid = threadIdx.x;
    const int warp = tid >> 5, lane = tid & 31;
    const int qt = blockIdx.x, h = blockIdx.y, b = blockIdx.z;
    const uint32_t swx = (lane & 7) << 4;

    const long long qrow0 = (long long)(b * S_LEN + qt * 128);
    const char* Qhg = (const char*)qh_ + ((((size_t)b * 16 + qt) * 16 + h) << 14);
    const char* Qlg = (const char*)ql_ + ((((size_t)b * 16 + qt) * 16 + h) << 14);
    const char* Khg = (const char*)kh_;
    const char* Klg = (const char*)kl_;
    const char* Vhg = (const char*)vth_;
    const char* Vlg = (const char*)vtl_;

    if (tid == 0) {
        MBAR_INIT(mbq, 1);
        MBAR_INIT(mbk0, 1);
        MBAR_INIT(mbk1, 1);
        FENCE_ASYNC_SHARED();
    }
    __syncthreads();

    auto loadQ = [&]() {
        if (tid == 0) {
            MBAR_EXPECT(mbq, 2 * FQ_TILE);
            BULK_CP(db,           Qhg, FQ_TILE, mbq);
            BULK_CP(db + FQ_TILE, Qlg, FQ_TILE, mbq);
        }
    };
    auto loadKV = [&](int kt, int buf) {
        if (tid == 0) {
            const uint32_t s = db + 2 * FQ_TILE + buf * FB_STAGE;
            const uint32_t mb = buf ? mbk1 : mbk0;
            MBAR_EXPECT(mb, FB_STAGE);
            size_t toff = (((size_t)b * 32 + kt) * 16 + h) << 13;
            BULK_CP(s,               Khg + toff, FK_TILE, mb);
            BULK_CP(s + FK_TILE,     Klg + toff, FK_TILE, mb);
            BULK_CP(s + 2 * FK_TILE, Vhg + toff, FK_TILE, mb);
            BULK_CP(s + 3 * FK_TILE, Vlg + toff, FK_TILE, mb);
        }
    };

    float accO[2][8][4];
#pragma unroll
    for (int mt = 0; mt < 2; ++mt)
#pragma unroll
        for (int i = 0; i < 8; ++i)
#pragma unroll
            for (int e = 0; e < 4; ++e) accO[mt][i][e] = 0.f;
    float fm[2][2] = {{-1e30f, -1e30f}, {-1e30f, -1e30f}};
    float fl[2][2] = {{0.f, 0.f}, {0.f, 0.f}};
    uint32_t qfh[2][4][4];

    loadQ();
    loadKV(0, 0);
    loadKV(1, 1);

    const uint32_t qRow = (warp * 32 + (lane & 15)) * 128;
    const uint32_t xQ = (lane >> 4) * 16;
    const int g = lane >> 3;
    const uint32_t kRow = ((g >> 1) * 8 + (lane & 7)) * 128;
    const uint32_t xKV = (g & 1) * 16;

    int ph[2] = { 0, 0 };
    const int NT64 = S_LEN / 64;   // 32
    for (int kt = 0; kt < NT64; ++kt) {
        const int buf = kt & 1;
        mbar_wait(buf ? mbk1 : mbk0, ph[buf]);
        ph[buf] ^= 1;
        if (kt == 0) {
            mbar_wait(mbq, 0);
#pragma unroll
            for (int mt = 0; mt < 2; ++mt)
#pragma unroll
                for (int ks = 0; ks < 4; ++ks)
                    LDSM4(qfh[mt][ks], db + qRow + mt * 2048 + ((xQ + ks * 32) ^ swx));
        }
        const uint32_t s = db + 2 * FQ_TILE + buf * FB_STAGE;

        // ---- S = Q @ K^T over 64 keys (3 products) ----
        float accS[2][8][4];
#pragma unroll
        for (int mt = 0; mt < 2; ++mt)
#pragma unroll
            for (int i = 0; i < 8; ++i)
#pragma unroll
                for (int e = 0; e < 4; ++e) accS[mt][i][e] = 0.f;
#pragma unroll
        for (int ks = 0; ks < 4; ++ks) {
            uint32_t qfl0[4], qfl1[4];
            LDSM4(qfl0, db + FQ_TILE + qRow + 0 * 2048 + ((xQ + ks * 32) ^ swx));
            LDSM4(qfl1, db + FQ_TILE + qRow + 1 * 2048 + ((xQ + ks * 32) ^ swx));
#pragma unroll
            for (int ntp = 0; ntp < 4; ++ntp) {
                const uint32_t kA = s + kRow + ntp * 2048 + ((xKV + ks * 32) ^ swx);
                uint32_t th[4], tl[4];
                LDSM4(th, kA);
                LDSM4(tl, kA + FK_TILE);
                uint32_t bh0[2] = { th[0], th[1] }, bh1[2] = { th[2], th[3] };
                uint32_t bl0[2] = { tl[0], tl[1] }, bl1[2] = { tl[2], tl[3] };
                MMA_BF16(accS[0][2*ntp],   qfh[0][ks], bh0);
                MMA_BF16(accS[0][2*ntp],   qfh[0][ks], bl0);
                MMA_BF16(accS[0][2*ntp],   qfl0,       bh0);
                MMA_BF16(accS[0][2*ntp+1], qfh[0][ks], bh1);
                MMA_BF16(accS[0][2*ntp+1], qfh[0][ks], bl1);
                MMA_BF16(accS[0][2*ntp+1], qfl0,       bh1);
                MMA_BF16(accS[1][2*ntp],   qfh[1][ks], bh0);
                MMA_BF16(accS[1][2*ntp],   qfh[1][ks], bl0);
                MMA_BF16(accS[1][2*ntp],   qfl1,       bh0);
                MMA_BF16(accS[1][2*ntp+1], qfh[1][ks], bh1);
                MMA_BF16(accS[1][2*ntp+1], qfh[1][ks], bl1);
                MMA_BF16(accS[1][2*ntp+1], qfl1,       bh1);
            }
        }

        // ---- online softmax ----
#pragma unroll
        for (int mt = 0; mt < 2; ++mt) {
            float mx0 = -1e30f, mx1 = -1e30f;
#pragma unroll
            for (int nt = 0; nt < 8; ++nt) {
                mx0 = fmaxf(mx0, fmaxf(accS[mt][nt][0], accS[mt][nt][1]));
                mx1 = fmaxf(mx1, fmaxf(accS[mt][nt][2], accS[mt][nt][3]));
            }
            mx0 = fmaxf(mx0, __shfl_xor_sync(0xffffffffu, mx0, 1));
            mx0 = fmaxf(mx0, __shfl_xor_sync(0xffffffffu, mx0, 2));
            mx1 = fmaxf(mx1, __shfl_xor_sync(0xffffffffu, mx1, 1));
            mx1 = fmaxf(mx1, __shfl_xor_sync(0xffffffffu, mx1, 2));
            float mn0 = fmaxf(fm[mt][0], mx0), mn1 = fmaxf(fm[mt][1], mx1);
            float c0 = __expf(fm[mt][0] - mn0), c1 = __expf(fm[mt][1] - mn1);
            fm[mt][0] = mn0; fm[mt][1] = mn1;
            float s0 = 0.f, s1 = 0.f;
#pragma unroll
            for (int nt = 0; nt < 8; ++nt) {
                accS[mt][nt][0] = __expf(accS[mt][nt][0] - mn0);
                accS[mt][nt][1] = __expf(accS[mt][nt][1] - mn0);
                accS[mt][nt][2] = __expf(accS[mt][nt][2] - mn1);
                accS[mt][nt][3] = __expf(accS[mt][nt][3] - mn1);
                s0 += accS[mt][nt][0] + accS[mt][nt][1];
                s1 += accS[mt][nt][2] + accS[mt][nt][3];
            }
            s0 += __shfl_xor_sync(0xffffffffu, s0, 1);
            s0 += __shfl_xor_sync(0xffffffffu, s0, 2);
            s1 += __shfl_xor_sync(0xffffffffu, s1, 1);
            s1 += __shfl_xor_sync(0xffffffffu, s1, 2);
            fl[mt][0] = fl[mt][0] * c0 + s0;
            fl[mt][1] = fl[mt][1] * c1 + s1;
#pragma unroll
            for (int nt = 0; nt < 8; ++nt) {
                accO[mt][nt][0] *= c0; accO[mt][nt][1] *= c0;
                accO[mt][nt][2] *= c1; accO[mt][nt][3] *= c1;
            }
        }

        // ---- O += P @ V ----
#pragma unroll
        for (int kg = 0; kg < 4; ++kg) {
            uint32_t pah[2][4], pal[2][4];
#pragma unroll
            for (int mt = 0; mt < 2; ++mt) {
                split_pack(accS[mt][2*kg][0],   accS[mt][2*kg][1],   pah[mt][0], pal[mt][0]);
                split_pack(accS[mt][2*kg][2],   accS[mt][2*kg][3],   pah[mt][1], pal[mt][1]);
                split_pack(accS[mt][2*kg+1][0], accS[mt][2*kg+1][1], pah[mt][2], pal[mt][2]);
                split_pack(accS[mt][2*kg+1][2], accS[mt][2*kg+1][3], pah[mt][3], pal[mt][3]);
            }
#pragma unroll
            for (int ntp = 0; ntp < 4; ++ntp) {
                const uint32_t vA = s + 2 * FK_TILE + kRow + ntp * 2048 + ((xKV + kg * 32) ^ swx);
                uint32_t th[4], tl[4];
                LDSM4(th, vA);
                LDSM4(tl, vA + FK_TILE);
                uint32_t bh0[2] = { th[0], th[1] }, bh1[2] = { th[2], th[3] };
                uint32_t bl0[2] = { tl[0], tl[1] }, bl1[2] = { tl[2], tl[3] };
#pragma unroll
                for (int mt = 0; mt < 2; ++mt) {
                    MMA_BF16(accO[mt][2*ntp],   pah[mt], bh0);
                    MMA_BF16(accO[mt][2*ntp],   pah[mt], bl0);
                    MMA_BF16(accO[mt][2*ntp],   pal[mt], bh0);
                    MMA_BF16(accO[mt][2*ntp+1], pah[mt], bh1);
                    MMA_BF16(accO[mt][2*ntp+1], pah[mt], bl1);
                    MMA_BF16(accO[mt][2*ntp+1], pal[mt], bh1);
                }
            }
        }
        __syncthreads();
        if (kt + 2 < NT64) loadKV(kt + 2, buf);
    }

    // ---- epilogue: write into A-packed layout for proj_out (k_chunk = h) ----
#pragma unroll
    for (int mt = 0; mt < 2; ++mt) {
        const float inv0 = 1.0f / fl[mt][0], inv1 = 1.0f / fl[mt][1];
        const long long tok0 = qrow0 + warp * 32 + mt * 16 + (lane >> 2);
        const int cb = (lane & 3) * 2;
#pragma unroll
        for (int nt = 0; nt < 8; ++nt) {
            int d = cb + nt * 8;
            uint32_t hp, lp;
            long long t0 = tok0, t1 = tok0 + 8;
            size_t dst0 = ((((size_t)(t0 >> 7)) * 16 + h) << 14) + swz((int)(t0 & 127), d * 2);
            size_t dst1 = ((((size_t)(t1 >> 7)) * 16 + h) << 14) + swz((int)(t1 & 127), d * 2);
            split_pack(accO[mt][nt][0] * inv0, accO[mt][nt][1] * inv0, hp, lp);
            *(uint32_t*)((char*)oh_ + dst0) = hp;
            *(uint32_t*)((char*)ol_ + dst0) = lp;
            split_pack(accO[mt][nt][2] * inv1, accO[mt][nt][3] * inv1, hp, lp);
            *(uint32_t*)((char*)oh_ + dst1) = hp;
            *(uint32_t*)((char*)ol_ + dst1) = lp;
        }
    }
}

// ===================== host =====================
static inline void* sym(const void* s) { void* p; cudaGetSymbolAddress(&p, s); return p; }

extern "C" void kernel_launch(void* const* d_in, const int* in_sizes, int n_in,
                              void* d_out, int out_size) {
    const float* v  = (const float*)d_in[0];
    const float* k  = (const float*)d_in[1];
    const float* q  = (const float*)d_in[2];
    const float* Wv = (const float*)d_in[3];
    const float* bv = (const float*)d_in[4];
    const float* Wk = (const float*)d_in[5];
    const float* bk = (const float*)d_in[6];
    const float* Wq = (const float*)d_in[7];
    const float* bq = (const float*)d_in[8];
    const float* Wo = (const float*)d_in[9];
    const float* bo = (const float*)d_in[10];

    __nv_bfloat16 *qh=(__nv_bfloat16*)sym(g_qh), *ql=(__nv_bfloat16*)sym(g_ql);
    __nv_bfloat16 *kh=(__nv_bfloat16*)sym(g_kh), *kl=(__nv_bfloat16*)sym(g_kl);
    __nv_bfloat16 *vh=(__nv_bfloat16*)sym(g_vh), *vl=(__nv_bfloat16*)sym(g_vl);
    __nv_bfloat16 *Wqh=(__nv_bfloat16*)sym(g_Wqh), *Wql=(__nv_bfloat16*)sym(g_Wql);
    __nv_bfloat16 *Wkh=(__nv_bfloat16*)sym(g_Wkh), *Wkl=(__nv_bfloat16*)sym(g_Wkl);
    __nv_bfloat16 *Wvh=(__nv_bfloat16*)sym(g_Wvh), *Wvl=(__nv_bfloat16*)sym(g_Wvl);
    __nv_bfloat16 *Woh=(__nv_bfloat16*)sym(g_Woh), *Wol=(__nv_bfloat16*)sym(g_Wol);
    __nv_bfloat16 *qph=(__nv_bfloat16*)sym(g_qph), *qpl=(__nv_bfloat16*)sym(g_qpl);
    __nv_bfloat16 *kph=(__nv_bfloat16*)sym(g_kph), *kpl=(__nv_bfloat16*)sym(g_kpl);
    __nv_bfloat16 *vTh=(__nv_bfloat16*)sym(g_vTh), *vTl=(__nv_bfloat16*)sym(g_vTl);
    __nv_bfloat16 *ath=(__nv_bfloat16*)sym(g_ath), *atl=(__nv_bfloat16*)sym(g_atl);

    cudaFuncSetAttribute(proj_qkv, cudaFuncAttributeMaxDynamicSharedMemorySize, G_SMEM);
    cudaFuncSetAttribute(proj_out, cudaFuncAttributeMaxDynamicSharedMemorySize, G_SMEM);
    cudaFuncSetAttribute(flash_attn, cudaFuncAttributeMaxDynamicSharedMemorySize, FB_SMEM);

    // launch 0: merged hi/lo splits into packed+swizzled layouts
    cvt_all<<<16384, 256>>>(q, k, v, Wq, Wk, Wv, Wo,
                            qh, ql, kh, kl, vh, vl,
                            Wqh, Wql, Wkh, Wkl, Wvh, Wvl, Woh, Wol);

    // launch 1: merged Q/K/V projections (128x128 tiles, 3-stage pipeline)
    proj_qkv<<<dim3(8, 32, 3), 256, G_SMEM>>>(
        qh, ql, kh, kl, vh, vl,
        Wqh, Wql, Wkh, Wkl, Wvh, Wvl,
        bq, bk, bv, qph, qpl, kph, kpl, vTh, vTl);

    // launch 2: fused flash attention (2 CTA/SM)
    flash_attn<<<dim3(S_LEN / 128, NHEAD, 2), 128, FB_SMEM>>>(
        qph, qpl, kph, kpl, vTh, vTl, ath, atl);

    // launch 3: final projection (128x128 tiles, 3-stage pipeline)
    proj_out<<<dim3(8, 32), 256, G_SMEM>>>(ath, atl, Woh, Wol, bo, (float*)d_out);
}

// round 16
// speedup vs baseline: 1.5946x; 1.0627x over previous
#include <cuda_runtime.h>
#include <cuda_bf16.h>
#include <cstdint>
#include <cstddef>

#define S_LEN  2048
#define DMODEL 1024
#define NHEAD  16
#define DK     64
#define NTOK   4096

// ===================== low-level helpers (base sm_103 target safe) =====================
__device__ __forceinline__ uint32_t smem_u32(const void* p) {
    uint32_t a;
    asm("{ .reg .u64 t; cvta.to.shared.u64 t, %1; cvt.u32.u64 %0, t; }" : "=r"(a) : "l"(p));
    return a;
}
#define LDSM4(d, addr) \
    asm volatile("ldmatrix.sync.aligned.m8n8.x4.shared.b16 {%0,%1,%2,%3}, [%4];" \
        : "=r"((d)[0]), "=r"((d)[1]), "=r"((d)[2]), "=r"((d)[3]) : "r"(addr))
#define MMA_BF16(c, a, b) \
    asm volatile("mma.sync.aligned.m16n8k16.row.col.f32.bf16.bf16.f32 " \
        "{%0,%1,%2,%3}, {%4,%5,%6,%7}, {%8,%9}, {%0,%1,%2,%3};" \
        : "+f"((c)[0]), "+f"((c)[1]), "+f"((c)[2]), "+f"((c)[3]) \
        : "r"((a)[0]), "r"((a)[1]), "r"((a)[2]), "r"((a)[3]), "r"((b)[0]), "r"((b)[1]))

#define BULK_CP(dst, src, size, mbar) \
    asm volatile("cp.async.bulk.shared::cluster.global.mbarrier::complete_tx::bytes " \
        "[%0], [%1], %2, [%3];" \
        :: "r"((uint32_t)(dst)), "l"(src), "r"((uint32_t)(size)), "r"((uint32_t)(mbar)) : "memory")
#define MBAR_INIT(addr, cnt) \
    asm volatile("mbarrier.init.shared.b64 [%0], %1;" :: "r"((uint32_t)(addr)), "r"((uint32_t)(cnt)) : "memory")
#define MBAR_EXPECT(addr, bytes) \
    asm volatile("mbarrier.arrive.expect_tx.shared.b64 _, [%0], %1;" \
        :: "r"((uint32_t)(addr)), "r"((uint32_t)(bytes)) : "memory")
#define FENCE_ASYNC_SHARED() asm volatile("fence.proxy.async.shared::cta;" ::: "memory")

__device__ __forceinline__ void mbar_wait(uint32_t mbar, int phase) {
    asm volatile(
        "{\n\t.reg .pred P1;\n\t"
        "WAIT_LOOP_%=:\n\t"
        "mbarrier.try_wait.parity.acquire.cta.shared::cta.b64 P1, [%0], %1, 0x989680;\n\t"
        "@P1 bra.uni WAIT_DONE_%=;\n\t"
        "bra.uni WAIT_LOOP_%=;\n\t"
        "WAIT_DONE_%=:\n\t}"
        :: "r"(mbar), "r"((uint32_t)phase) : "memory");
}

__device__ __forceinline__ void split2(float v, __nv_bfloat16& h, __nv_bfloat16& l) {
    h = __float2bfloat16(v);
    l = __float2bfloat16(v - __bfloat162float(h));
}
__device__ __forceinline__ void split_pack(float x, float y, uint32_t& hp, uint32_t& lp) {
    __nv_bfloat16 hx, lx, hy, ly;
    split2(x, hx, lx); split2(y, hy, ly);
    __nv_bfloat162 h2(hx, hy), l2(lx, ly);
    hp = *reinterpret_cast<uint32_t*>(&h2);
    lp = *reinterpret_cast<uint32_t*>(&l2);
}
__device__ __forceinline__ uint32_t swz(int r, int x) {
    return (uint32_t)(r * 128 + (x ^ ((r & 7) << 4)));
}

// ===================== scratch (all packed tile layouts) =====================
__device__ __nv_bfloat16 g_qh[NTOK*DMODEL], g_ql[NTOK*DMODEL];     // A-packed [32][16] tiles
__device__ __nv_bfloat16 g_kh[NTOK*DMODEL], g_kl[NTOK*DMODEL];
__device__ __nv_bfloat16 g_vh[NTOK*DMODEL], g_vl[NTOK*DMODEL];
__device__ __nv_bfloat16 g_Wqh[DMODEL*DMODEL], g_Wql[DMODEL*DMODEL]; // B-packed [8][16]
__device__ __nv_bfloat16 g_Wkh[DMODEL*DMODEL], g_Wkl[DMODEL*DMODEL];
__device__ __nv_bfloat16 g_Wvh[DMODEL*DMODEL], g_Wvl[DMODEL*DMODEL];
__device__ __nv_bfloat16 g_Woh[DMODEL*DMODEL], g_Wol[DMODEL*DMODEL];
__device__ __nv_bfloat16 g_qph[NTOK*DMODEL], g_qpl[NTOK*DMODEL];   // [b][qt16][h] 16KB tiles
__device__ __nv_bfloat16 g_kph[NTOK*DMODEL], g_kpl[NTOK*DMODEL];   // [b][kt32][h] 8KB tiles
__device__ __nv_bfloat16 g_vTh[NTOK*DMODEL], g_vTl[NTOK*DMODEL];   // [b][kt32][h] 8KB V^T tiles
__device__ __nv_bfloat16 g_ath[NTOK*DMODEL], g_atl[NTOK*DMODEL];   // A-packed [32][16]

// ===================== merged fp32 -> packed swizzled (bf16 hi, bf16 lo) =====================
__global__ __launch_bounds__(256) void cvt_all(
    const float* __restrict__ q, const float* __restrict__ k, const float* __restrict__ v,
    const float* __restrict__ Wq, const float* __restrict__ Wk,
    const float* __restrict__ Wv, const float* __restrict__ Wo,
    __nv_bfloat16* qh, __nv_bfloat16* ql, __nv_bfloat16* kh, __nv_bfloat16* kl,
    __nv_bfloat16* vh, __nv_bfloat16* vl,
    __nv_bfloat16* Wqh, __nv_bfloat16* Wql, __nv_bfloat16* Wkh, __nv_bfloat16* Wkl,
    __nv_bfloat16* Wvh, __nv_bfloat16* Wvl, __nv_bfloat16* Woh, __nv_bfloat16* Wol)
{
    int bid = blockIdx.x;
    const float* src; __nv_bfloat16 *hi, *lo; int lb;
    if      (bid < 4096)  { src = q;  hi = qh;  lo = ql;  lb = bid; }
    else if (bid < 8192)  { src = k;  hi = kh;  lo = kl;  lb = bid - 4096; }
    else if (bid < 12288) { src = v;  hi = vh;  lo = vl;  lb = bid - 8192; }
    else if (bid < 13312) { src = Wq; hi = Wqh; lo = Wql; lb = bid - 12288; }
    else if (bid < 14336) { src = Wk; hi = Wkh; lo = Wkl; lb = bid - 13312; }
    else if (bid < 15360) { src = Wv; hi = Wvh; lo = Wvl; lb = bid - 14336; }
    else                  { src = Wo; hi = Woh; lo = Wol; lb = bid - 15360; }
    int i = (lb * 256 + threadIdx.x) * 4;
    float4 val = *(const float4*)(src + i);
    uint32_t hp0, lp0, hp1, lp1;
    split_pack(val.x, val.y, hp0, lp0);
    split_pack(val.z, val.w, hp1, lp1);
    int row = i >> 10, kk = i & 1023;
    int mb = row >> 7, r = row & 127, kc = kk >> 6, c = kk & 63;
    size_t dst = (((size_t)mb * 16 + kc) << 14) + swz(r, c * 2);
    *(uint32_t*)((char*)hi + dst)     = hp0;
    *(uint32_t*)((char*)hi + dst + 4) = hp1;
    *(uint32_t*)((char*)lo + dst)     = lp0;
    *(uint32_t*)((char*)lo + dst + 4) = lp1;
}

// ===================== HMMA bf16x3 GEMM body (64x128 tile, BK=64, 2 CTA/SM bulk pipeline) =====================
// 128 threads = 4 warps (64x32 warp tile). Stage = [Ahi 8K, Alo 8K, Bhi 16K, Blo 16K] = 48KB.
// ep: 0 fp32+bias | 1 Q-packed | 2 K-packed | 3 V^T-packed  (1-3: bf16 hi/lo (+bias)*scale)
#define G_TILE 16384
#define G_HALF 8192
#define G_STAGE (2 * G_HALF + 2 * G_TILE)  // 49152
#define G_SMEM (1024 + 2 * G_STAGE)        // 99328

__device__ __forceinline__ void gemm_body(
    int ep,
    const char* Ah, const char* Al, const char* Bh, const char* Bl,
    float* C32, __nv_bfloat16* Chi, __nv_bfloat16* Clo,
    const float* bias, float scale, char* smem)
{
    const uint32_t sbase = smem_u32(smem);
    const uint32_t dbase = sbase + 1024;

    const int tid = threadIdx.x;
    const int warp = tid >> 5, lane = tid & 31;
    const int wn0 = warp * 32;                 // warp tile: all 64 M rows x 32 N cols
    const int m0 = blockIdx.y * 64;
    const int n0 = blockIdx.x * 128;
    const int tileA = blockIdx.y >> 1;         // packed A tile index (128 rows)
    const int halfA = blockIdx.y & 1;          // which 64-row half (8KB contiguous)
    const uint32_t swx = (lane & 7) << 4;

    if (tid == 0) {
        MBAR_INIT(sbase, 1);
        MBAR_INIT(sbase + 16, 1);
        FENCE_ASYNC_SHARED();
    }
    __syncthreads();

    auto load_chunk = [&](int c, int stg) {
        if (tid == 0) {
            const uint32_t s = dbase + stg * G_STAGE;
            const uint32_t mb = sbase + stg * 16;
            MBAR_EXPECT(mb, G_STAGE);
            size_t at = (((size_t)(tileA * 16 + c)) << 14) + (size_t)halfA * G_HALF;
            size_t bt = ((size_t)(blockIdx.x * 16 + c)) << 14;
            BULK_CP(s,                       Ah + at, G_HALF, mb);
            BULK_CP(s + G_HALF,              Al + at, G_HALF, mb);
            BULK_CP(s + 2 * G_HALF,          Bh + bt, G_TILE, mb);
            BULK_CP(s + 2 * G_HALF + G_TILE, Bl + bt, G_TILE, mb);
        }
    };

    float acc[4][4][4];
#pragma unroll
    for (int i = 0; i < 4; ++i)
#pragma unroll
        for (int j = 0; j < 4; ++j)
#pragma unroll
            for (int e = 0; e < 4; ++e) acc[i][j][e] = 0.f;

    const uint32_t aRow = (lane & 15) * 128;   // + mt*16*128 inside loop (rows 0..63 of half)
    const int g = lane >> 3;
    const uint32_t bRow = (wn0 + (g >> 1) * 8 + (lane & 7)) * 128;
    const uint32_t xA = (lane >> 4) * 16;
    const uint32_t xB = (g & 1) * 16;

    load_chunk(0, 0);
    load_chunk(1, 1);

    int ph[2] = { 0, 0 };
    const int chunks = 16;
    for (int c = 0; c < chunks; ++c) {
        const int stg = c & 1;
        mbar_wait(sbase + stg * 16, ph[stg]);
        ph[stg] ^= 1;

        const uint32_t s = dbase + stg * G_STAGE;
#pragma unroll
        for (int ks = 0; ks < 4; ++ks) {
            const uint32_t kb = ks * 32;
            uint32_t ah[4][4], al[4][4];
#pragma unroll
            for (int mt = 0; mt < 4; ++mt) {
                uint32_t off = aRow + mt * 2048 + ((xA + kb) ^ swx);
                LDSM4(ah[mt], s + off);
                LDSM4(al[mt], s + G_HALF + off);
            }
            uint32_t bh[4][2], bl[4][2];
#pragma unroll
            for (int ntp = 0; ntp < 2; ++ntp) {
                uint32_t off = bRow + ntp * 2048 + ((xB + kb) ^ swx);
                uint32_t t[4];
                LDSM4(t, s + 2 * G_HALF + off);
                bh[ntp*2][0] = t[0]; bh[ntp*2][1] = t[1];
                bh[ntp*2+1][0] = t[2]; bh[ntp*2+1][1] = t[3];
                LDSM4(t, s + 2 * G_HALF + G_TILE + off);
                bl[ntp*2][0] = t[0]; bl[ntp*2][1] = t[1];
                bl[ntp*2+1][0] = t[2]; bl[ntp*2+1][1] = t[3];
            }
#pragma unroll
            for (int mt = 0; mt < 4; ++mt)
#pragma unroll
                for (int nt = 0; nt < 4; ++nt) {
                    MMA_BF16(acc[mt][nt], ah[mt], bh[nt]);
                    MMA_BF16(acc[mt][nt], ah[mt], bl[nt]);
                    MMA_BF16(acc[mt][nt], al[mt], bh[nt]);
                }
        }
        __syncthreads();   // all reads of stg done before refill
        if (c + 2 < chunks) load_chunk(c + 2, stg);
    }

#pragma unroll
    for (int mt = 0; mt < 4; ++mt) {
#pragma unroll
        for (int nt = 0; nt < 4; ++nt) {
            int row0 = m0 + mt * 16 + (lane >> 2);
            int row1 = row0 + 8;
            int col = n0 + wn0 + nt * 8 + (lane & 3) * 2;
            float p0 = acc[mt][nt][0], p1 = acc[mt][nt][1];
            float p2 = acc[mt][nt][2], p3 = acc[mt][nt][3];
            if (ep == 0) {
                float b0 = bias[col], b1 = bias[col + 1];
                *(float2*)&C32[(long long)row0 * DMODEL + col] = make_float2(p0 + b0, p1 + b1);
                *(float2*)&C32[(long long)row1 * DMODEL + col] = make_float2(p2 + b0, p3 + b1);
            } else if (ep == 1 || ep == 2) {
                float b0 = bias[col], b1 = bias[col + 1];
                float v0 = (p0 + b0) * scale, v1 = (p1 + b1) * scale;
                float v2 = (p2 + b0) * scale, v3 = (p3 + b1) * scale;
                int h = col >> 6, cc = col & 63;
                int rows[2] = { row0, row1 };
                uint32_t hps[2], lps[2];
                split_pack(v0, v1, hps[0], lps[0]);
                split_pack(v2, v3, hps[1], lps[1]);
#pragma unroll
                for (int e = 0; e < 2; ++e) {
                    int t = rows[e];
                    size_t dst;
                    if (ep == 1) {   // Q-packed: [b][qt128][h] 16KB
                        dst = ((((size_t)(t >> 11) * 16 + ((t & 2047) >> 7)) * 16 + h) << 14)
                            + swz(t & 127, cc * 2);
                    } else {         // K-packed: [b][kt64][h] 8KB
                        dst = ((((size_t)(t >> 11) * 32 + ((t & 2047) >> 6)) * 16 + h) << 13)
                            + swz(t & 63, cc * 2);
                    }
                    *(uint32_t*)((char*)Chi + dst) = hps[e];
                    *(uint32_t*)((char*)Clo + dst) = lps[e];
                }
            } else {  // ep == 3 : V^T-packed: [b][kt64][h] 8KB, rows=d cols=key
                float vals[4] = { p0, p1, p2, p3 };
                int rows[4] = { row0, row0, row1, row1 };
                int cols[4] = { col, col + 1, col, col + 1 };
#pragma unroll
                for (int e = 0; e < 4; ++e) {
                    float vv = vals[e] + bias[cols[e]];
                    __nv_bfloat16 h2, l2; split2(vv, h2, l2);
                    int t = rows[e];
                    int hh = cols[e] >> 6, d = cols[e] & 63;
                    size_t dst = ((((size_t)(t >> 11) * 32 + ((t & 2047) >> 6)) * 16 + hh) << 13)
                               + swz(d, (t & 63) * 2);
                    *(__nv_bfloat16*)((char*)Chi + dst) = h2;
                    *(__nv_bfloat16*)((char*)Clo + dst) = l2;
                }
            }
        }
    }
}

// merged Q/K/V projections: blockIdx.z selects operands
__global__ __launch_bounds__(128, 2) void proj_qkv(
    const __nv_bfloat16* qh, const __nv_bfloat16* ql,
    const __nv_bfloat16* kh, const __nv_bfloat16* kl,
    const __nv_bfloat16* vh, const __nv_bfloat16* vl,
    const __nv_bfloat16* Wqh, const __nv_bfloat16* Wql,
    const __nv_bfloat16* Wkh, const __nv_bfloat16* Wkl,
    const __nv_bfloat16* Wvh, const __nv_bfloat16* Wvl,
    const float* bq, const float* bk, const float* bv,
    __nv_bfloat16* qph, __nv_bfloat16* qpl,
    __nv_bfloat16* kph, __nv_bfloat16* kpl,
    __nv_bfloat16* vTh, __nv_bfloat16* vTl)
{
    extern __shared__ char smem[];
    int z = blockIdx.z;
    if (z == 0) {
        gemm_body(1, (const char*)qh, (const char*)ql, (const char*)Wqh, (const char*)Wql,
                  nullptr, qph, qpl, bq, 0.125f, smem);
    } else if (z == 1) {
        gemm_body(2, (const char*)kh, (const char*)kl, (const char*)Wkh, (const char*)Wkl,
                  nullptr, kph, kpl, bk, 1.0f, smem);
    } else {
        gemm_body(3, (const char*)vh, (const char*)vl, (const char*)Wvh, (const char*)Wvl,
                  nullptr, vTh, vTl, bv, 1.0f, smem);
    }
}

// final projection (fp32 out + bias)
__global__ __launch_bounds__(128, 2) void proj_out(
    const __nv_bfloat16* ath, const __nv_bfloat16* atl,
    const __nv_bfloat16* Woh, const __nv_bfloat16* Wol,
    const float* bo, float* out)
{
    extern __shared__ char smem[];
    gemm_body(0, (const char*)ath, (const char*)atl, (const char*)Woh, (const char*)Wol,
              out, nullptr, nullptr, bo, 1.0f, smem);
}

// ===================== fused flash attention (packed tiles, 8KB/16KB bulk copies) =====================
#define FQ_TILE 16384
#define FK_TILE 8192
#define FB_STAGE (4 * FK_TILE)                    // 32768
#define FB_SMEM (1024 + 2 * FQ_TILE + 2 * FB_STAGE)  // 99328

__global__ __launch_bounds__(128, 2) void flash_attn(
    const __nv_bfloat16* __restrict__ qh_, const __nv_bfloat16* __restrict__ ql_,
    const __nv_bfloat16* __restrict__ kh_, const __nv_bfloat16* __restrict__ kl_,
    const __nv_bfloat16* __restrict__ vth_, const __nv_bfloat16* __restrict__ vtl_,
    __nv_bfloat16* __restrict__ oh_, __nv_bfloat16* __restrict__ ol_)
{
    extern __shared__ char smem[];
    const uint32_t sb = smem_u32(smem);
    const uint32_t mbq = sb, mbk0 = sb + 16, mbk1 = sb + 32;
    const uint32_t db = sb + 1024;
    const int tid = threadIdx.x;
    const int warp = tid >> 5, lane = tid & 31;
    const int qt = blockIdx.x, h = blockIdx.y, b = blockIdx.z;
    const uint32_t swx = (lane & 7) << 4;

    const long long qrow0 = (long long)(b * S_LEN + qt * 128);
    const char* Qhg = (const char*)qh_ + ((((size_t)b * 16 + qt) * 16 + h) << 14);
    const char* Qlg = (const char*)ql_ + ((((size_t)b * 16 + qt) * 16 + h) << 14);
    const char* Khg = (const char*)kh_;
    const char* Klg = (const char*)kl_;
    const char* Vhg = (const char*)vth_;
    const char* Vlg = (const char*)vtl_;

    if (tid == 0) {
        MBAR_INIT(mbq, 1);
        MBAR_INIT(mbk0, 1);
        MBAR_INIT(mbk1, 1);
        FENCE_ASYNC_SHARED();
    }
    __syncthreads();

    auto loadQ = [&]() {
        if (tid == 0) {
            MBAR_EXPECT(mbq, 2 * FQ_TILE);
            BULK_CP(db,           Qhg, FQ_TILE, mbq);
            BULK_CP(db + FQ_TILE, Qlg, FQ_TILE, mbq);
        }
    };
    auto loadKV = [&](int kt, int buf) {
        if (tid == 0) {
            const uint32_t s = db + 2 * FQ_TILE + buf * FB_STAGE;
            const uint32_t mb = buf ? mbk1 : mbk0;
            MBAR_EXPECT(mb, FB_STAGE);
            size_t toff = (((size_t)b * 32 + kt) * 16 + h) << 13;
            BULK_CP(s,               Khg + toff, FK_TILE, mb);
            BULK_CP(s + FK_TILE,     Klg + toff, FK_TILE, mb);
            BULK_CP(s + 2 * FK_TILE, Vhg + toff, FK_TILE, mb);
            BULK_CP(s + 3 * FK_TILE, Vlg + toff, FK_TILE, mb);
        }
    };

    float accO[2][8][4];
#pragma unroll
    for (int mt = 0; mt < 2; ++mt)
#pragma unroll
        for (int i = 0; i < 8; ++i)
#pragma unroll
            for (int e = 0; e < 4; ++e) accO[mt][i][e] = 0.f;
    float fm[2][2] = {{-1e30f, -1e30f}, {-1e30f, -1e30f}};
    float fl[2][2] = {{0.f, 0.f}, {0.f, 0.f}};
    uint32_t qfh[2][4][4];

    loadQ();
    loadKV(0, 0);
    loadKV(1, 1);

    const uint32_t qRow = (warp * 32 + (lane & 15)) * 128;
    const uint32_t xQ = (lane >> 4) * 16;
    const int g = lane >> 3;
    const uint32_t kRow = ((g >> 1) * 8 + (lane & 7)) * 128;
    const uint32_t xKV = (g & 1) * 16;

    int ph[2] = { 0, 0 };
    const int NT64 = S_LEN / 64;   // 32
    for (int kt = 0; kt < NT64; ++kt) {
        const int buf = kt & 1;
        mbar_wait(buf ? mbk1 : mbk0, ph[buf]);
        ph[buf] ^= 1;
        if (kt == 0) {
            mbar_wait(mbq, 0);
#pragma unroll
            for (int mt = 0; mt < 2; ++mt)
#pragma unroll
                for (int ks = 0; ks < 4; ++ks)
                    LDSM4(qfh[mt][ks], db + qRow + mt * 2048 + ((xQ + ks * 32) ^ swx));
        }
        const uint32_t s = db + 2 * FQ_TILE + buf * FB_STAGE;

        // ---- S = Q @ K^T over 64 keys (3 products) ----
        float accS[2][8][4];
#pragma unroll
        for (int mt = 0; mt < 2; ++mt)
#pragma unroll
            for (int i = 0; i < 8; ++i)
#pragma unroll
                for (int e = 0; e < 4; ++e) accS[mt][i][e] = 0.f;
#pragma unroll
        for (int ks = 0; ks < 4; ++ks) {
            uint32_t qfl0[4], qfl1[4];
            LDSM4(qfl0, db + FQ_TILE + qRow + 0 * 2048 + ((xQ + ks * 32) ^ swx));
            LDSM4(qfl1, db + FQ_TILE + qRow + 1 * 2048 + ((xQ + ks * 32) ^ swx));
#pragma unroll
            for (int ntp = 0; ntp < 4; ++ntp) {
                const uint32_t kA = s + kRow + ntp * 2048 + ((xKV + ks * 32) ^ swx);
                uint32_t th[4], tl[4];
                LDSM4(th, kA);
                LDSM4(tl, kA + FK_TILE);
                uint32_t bh0[2] = { th[0], th[1] }, bh1[2] = { th[2], th[3] };
                uint32_t bl0[2] = { tl[0], tl[1] }, bl1[2] = { tl[2], tl[3] };
                MMA_BF16(accS[0][2*ntp],   qfh[0][ks], bh0);
                MMA_BF16(accS[0][2*ntp],   qfh[0][ks], bl0);
                MMA_BF16(accS[0][2*ntp],   qfl0,       bh0);
                MMA_BF16(accS[0][2*ntp+1], qfh[0][ks], bh1);
                MMA_BF16(accS[0][2*ntp+1], qfh[0][ks], bl1);
                MMA_BF16(accS[0][2*ntp+1], qfl0,       bh1);
                MMA_BF16(accS[1][2*ntp],   qfh[1][ks], bh0);
                MMA_BF16(accS[1][2*ntp],   qfh[1][ks], bl0);
                MMA_BF16(accS[1][2*ntp],   qfl1,       bh0);
                MMA_BF16(accS[1][2*ntp+1], qfh[1][ks], bh1);
                MMA_BF16(accS[1][2*ntp+1], qfh[1][ks], bl1);
                MMA_BF16(accS[1][2*ntp+1], qfl1,       bh1);
            }
        }

        // ---- online softmax ----
#pragma unroll
        for (int mt = 0; mt < 2; ++mt) {
            float mx0 = -1e30f, mx1 = -1e30f;
#pragma unroll
            for (int nt = 0; nt < 8; ++nt) {
                mx0 = fmaxf(mx0, fmaxf(accS[mt][nt][0], accS[mt][nt][1]));
                mx1 = fmaxf(mx1, fmaxf(accS[mt][nt][2], accS[mt][nt][3]));
            }
            mx0 = fmaxf(mx0, __shfl_xor_sync(0xffffffffu, mx0, 1));
            mx0 = fmaxf(mx0, __shfl_xor_sync(0xffffffffu, mx0, 2));
            mx1 = fmaxf(mx1, __shfl_xor_sync(0xffffffffu, mx1, 1));
            mx1 = fmaxf(mx1, __shfl_xor_sync(0xffffffffu, mx1, 2));
            float mn0 = fmaxf(fm[mt][0], mx0), mn1 = fmaxf(fm[mt][1], mx1);
            float c0 = __expf(fm[mt][0] - mn0), c1 = __expf(fm[mt][1] - mn1);
            fm[mt][0] = mn0; fm[mt][1] = mn1;
            float s0 = 0.f, s1 = 0.f;
#pragma unroll
            for (int nt = 0; nt < 8; ++nt) {
                accS[mt][nt][0] = __expf(accS[mt][nt][0] - mn0);
                accS[mt][nt][1] = __expf(accS[mt][nt][1] - mn0);
                accS[mt][nt][2] = __expf(accS[mt][nt][2] - mn1);
                accS[mt][nt][3] = __expf(accS[mt][nt][3] - mn1);
                s0 += accS[mt][nt][0] + accS[mt][nt][1];
                s1 += accS[mt][nt][2] + accS[mt][nt][3];
            }
            s0 += __shfl_xor_sync(0xffffffffu, s0, 1);
            s0 += __shfl_xor_sync(0xffffffffu, s0, 2);
            s1 += __shfl_xor_sync(0xffffffffu, s1, 1);
            s1 += __shfl_xor_sync(0xffffffffu, s1, 2);
            fl[mt][0] = fl[mt][0] * c0 + s0;
            fl[mt][1] = fl[mt][1] * c1 + s1;
#pragma unroll
            for (int nt = 0; nt < 8; ++nt) {
                accO[mt][nt][0] *= c0; accO[mt][nt][1] *= c0;
                accO[mt][nt][2] *= c1; accO[mt][nt][3] *= c1;
            }
        }

        // ---- O += P @ V ----
#pragma unroll
        for (int kg = 0; kg < 4; ++kg) {
            uint32_t pah[2][4], pal[2][4];
#pragma unroll
            for (int mt = 0; mt < 2; ++mt) {
                split_pack(accS[mt][2*kg][0],   accS[mt][2*kg][1],   pah[mt][0], pal[mt][0]);
                split_pack(accS[mt][2*kg][2],   accS[mt][2*kg][3],   pah[mt][1], pal[mt][1]);
                split_pack(accS[mt][2*kg+1][0], accS[mt][2*kg+1][1], pah[mt][2], pal[mt][2]);
                split_pack(accS[mt][2*kg+1][2], accS[mt][2*kg+1][3], pah[mt][3], pal[mt][3]);
            }
#pragma unroll
            for (int ntp = 0; ntp < 4; ++ntp) {
                const uint32_t vA = s + 2 * FK_TILE + kRow + ntp * 2048 + ((xKV + kg * 32) ^ swx);
                uint32_t th[4], tl[4];
                LDSM4(th, vA);
                LDSM4(tl, vA + FK_TILE);
                uint32_t bh0[2] = { th[0], th[1] }, bh1[2] = { th[2], th[3] };
                uint32_t bl0[2] = { tl[0], tl[1] }, bl1[2] = { tl[2], tl[3] };
#pragma unroll
                for (int mt = 0; mt < 2; ++mt) {
                    MMA_BF16(accO[mt][2*ntp],   pah[mt], bh0);
                    MMA_BF16(accO[mt][2*ntp],   pah[mt], bl0);
                    MMA_BF16(accO[mt][2*ntp],   pal[mt], bh0);
                    MMA_BF16(accO[mt][2*ntp+1], pah[mt], bh1);
                    MMA_BF16(accO[mt][2*ntp+1], pah[mt], bl1);
                    MMA_BF16(accO[mt][2*ntp+1], pal[mt], bh1);
                }
            }
        }
        __syncthreads();
        if (kt + 2 < NT64) loadKV(kt + 2, buf);
    }

    // ---- epilogue: write into A-packed layout for proj_out (k_chunk = h) ----
#pragma unroll
    for (int mt = 0; mt < 2; ++mt) {
        const float inv0 = 1.0f / fl[mt][0], inv1 = 1.0f / fl[mt][1];
        const long long tok0 = qrow0 + warp * 32 + mt * 16 + (lane >> 2);
        const int cb = (lane & 3) * 2;
#pragma unroll
        for (int nt = 0; nt < 8; ++nt) {
            int d = cb + nt * 8;
            uint32_t hp, lp;
            long long t0 = tok0, t1 = tok0 + 8;
            size_t dst0 = ((((size_t)(t0 >> 7)) * 16 + h) << 14) + swz((int)(t0 & 127), d * 2);
            size_t dst1 = ((((size_t)(t1 >> 7)) * 16 + h) << 14) + swz((int)(t1 & 127), d * 2);
            split_pack(accO[mt][nt][0] * inv0, accO[mt][nt][1] * inv0, hp, lp);
            *(uint32_t*)((char*)oh_ + dst0) = hp;
            *(uint32_t*)((char*)ol_ + dst0) = lp;
            split_pack(accO[mt][nt][2] * inv1, accO[mt][nt][3] * inv1, hp, lp);
            *(uint32_t*)((char*)oh_ + dst1) = hp;
            *(uint32_t*)((char*)ol_ + dst1) = lp;
        }
    }
}

// ===================== host =====================
static inline void* sym(const void* s) { void* p; cudaGetSymbolAddress(&p, s); return p; }

extern "C" void kernel_launch(void* const* d_in, const int* in_sizes, int n_in,
                              void* d_out, int out_size) {
    const float* v  = (const float*)d_in[0];
    const float* k  = (const float*)d_in[1];
    const float* q  = (const float*)d_in[2];
    const float* Wv = (const float*)d_in[3];
    const float* bv = (const float*)d_in[4];
    const float* Wk = (const float*)d_in[5];
    const float* bk = (const float*)d_in[6];
    const float* Wq = (const float*)d_in[7];
    const float* bq = (const float*)d_in[8];
    const float* Wo = (const float*)d_in[9];
    const float* bo = (const float*)d_in[10];

    __nv_bfloat16 *qh=(__nv_bfloat16*)sym(g_qh), *ql=(__nv_bfloat16*)sym(g_ql);
    __nv_bfloat16 *kh=(__nv_bfloat16*)sym(g_kh), *kl=(__nv_bfloat16*)sym(g_kl);
    __nv_bfloat16 *vh=(__nv_bfloat16*)sym(g_vh), *vl=(__nv_bfloat16*)sym(g_vl);
    __nv_bfloat16 *Wqh=(__nv_bfloat16*)sym(g_Wqh), *Wql=(__nv_bfloat16*)sym(g_Wql);
    __nv_bfloat16 *Wkh=(__nv_bfloat16*)sym(g_Wkh), *Wkl=(__nv_bfloat16*)sym(g_Wkl);
    __nv_bfloat16 *Wvh=(__nv_bfloat16*)sym(g_Wvh), *Wvl=(__nv_bfloat16*)sym(g_Wvl);
    __nv_bfloat16 *Woh=(__nv_bfloat16*)sym(g_Woh), *Wol=(__nv_bfloat16*)sym(g_Wol);
    __nv_bfloat16 *qph=(__nv_bfloat16*)sym(g_qph), *qpl=(__nv_bfloat16*)sym(g_qpl);
    __nv_bfloat16 *kph=(__nv_bfloat16*)sym(g_kph), *kpl=(__nv_bfloat16*)sym(g_kpl);
    __nv_bfloat16 *vTh=(__nv_bfloat16*)sym(g_vTh), *vTl=(__nv_bfloat16*)sym(g_vTl);
    __nv_bfloat16 *ath=(__nv_bfloat16*)sym(g_ath), *atl=(__nv_bfloat16*)sym(g_atl);

    cudaFuncSetAttribute(proj_qkv, cudaFuncAttributeMaxDynamicSharedMemorySize, G_SMEM);
    cudaFuncSetAttribute(proj_out, cudaFuncAttributeMaxDynamicSharedMemorySize, G_SMEM);
    cudaFuncSetAttribute(flash_attn, cudaFuncAttributeMaxDynamicSharedMemorySize, FB_SMEM);

    // launch 0: merged hi/lo splits into packed+swizzled layouts
    cvt_all<<<16384, 256>>>(q, k, v, Wq, Wk, Wv, Wo,
                            qh, ql, kh, kl, vh, vl,
                            Wqh, Wql, Wkh, Wkl, Wvh, Wvl, Woh, Wol);

    // launch 1: merged Q/K/V projections (64x128 tiles, 2 CTA/SM)
    proj_qkv<<<dim3(8, 64, 3), 128, G_SMEM>>>(
        qh, ql, kh, kl, vh, vl,
        Wqh, Wql, Wkh, Wkl, Wvh, Wvl,
        bq, bk, bv, qph, qpl, kph, kpl, vTh, vTl);

    // launch 2: fused flash attention (2 CTA/SM)
    flash_attn<<<dim3(S_LEN / 128, NHEAD, 2), 128, FB_SMEM>>>(
        qph, qpl, kph, kpl, vTh, vTl, ath, atl);

    // launch 3: final projection (64x128 tiles, 2 CTA/SM)
    proj_out<<<dim3(8, 64), 128, G_SMEM>>>(ath, atl, Woh, Wol, bo, (float*)d_out);
}